// round 2
// baseline (speedup 1.0000x reference)
#include <cuda_runtime.h>
#include <math.h>

// ---------- scratch (device globals; no allocation allowed) ----------
__device__ float g_s1[768*64*751];
__device__ float g_s2[768*128*377];
__device__ float g_s3[768*128*191];
__device__ float g_mp[4*768*256];
__device__ float g_a [768*256];
__device__ float g_f1[160*8*256];
__device__ float g_f2[96*8*256];
__device__ float g_adj1[160*64];
__device__ float g_adj2[96*64];
__device__ float g_feats[32*4096];
__device__ float g_t1[32*256];
__device__ float g_t2[32*256];
__device__ float g_t3[32*128];

// ---------- conv1 (1->64,K=3,pad=1)+BN+ReLU+maxpool2(pad=1): x[768,1500]->out[768,64,751] ----------
__global__ void k_conv1(const float* __restrict__ x, const float* __restrict__ w,
                        const float* __restrict__ bn, float* __restrict__ out) {
    __shared__ float xs[516];
    __shared__ float ws[192];
    __shared__ float sc[64], sh[64];
    const int b = blockIdx.x, j0 = blockIdx.y * 256, tid = threadIdx.x;
    for (int i = tid; i < 192; i += 128) ws[i] = w[i];
    if (tid < 64) {
        float s = bn[tid] * rsqrtf(bn[192+tid] + 1e-5f);
        sc[tid] = s; sh[tid] = bn[64+tid] - bn[128+tid]*s;
    }
    const int base = 2*j0 - 2;
    for (int i = tid; i < 514; i += 128) {
        int gi = base + i;
        xs[i] = (gi >= 0 && gi < 1500) ? x[b*1500 + gi] : 0.f;
    }
    __syncthreads();
    const int j1 = j0 + 2*tid, j2 = j1 + 1;
    if (j1 > 750) return;
    float xv[6];
    #pragma unroll
    for (int i = 0; i < 6; i++) xv[i] = xs[4*tid + i];
    const int cb = 2*j1 - 1;
    const bool v0 = (cb >= 0), v1 = (cb + 1 < 1500), v3 = (cb + 3 < 1500);
    for (int oc = 0; oc < 64; oc++) {
        float w0 = ws[3*oc], w1 = ws[3*oc+1], w2 = ws[3*oc+2];
        float s = sc[oc], h = sh[oc], r[4];
        #pragma unroll
        for (int d = 0; d < 4; d++) {
            float t = fmaf(w2, xv[d+2], fmaf(w1, xv[d+1], w0*xv[d]));
            r[d] = fmaxf(fmaf(t, s, h), 0.f);
        }
        out[(b*64+oc)*751 + j1] = fmaxf(v0 ? r[0] : -1e30f, v1 ? r[1] : -1e30f);
        if (j2 <= 750)
            out[(b*64+oc)*751 + j2] = fmaxf(r[2], v3 ? r[3] : -1e30f);
    }
}

// ---------- generic conv (IC->128,K=3)+BN+ReLU+pool; tile 128oc x 32 pooled; thread: 8oc x 8 conv pos ----------
template<int IC, int PAD, int LIN, int JOUT>
__global__ __launch_bounds__(128)
void k_conv(const float* __restrict__ x, const float* __restrict__ w,
            const float* __restrict__ bn, float* __restrict__ out) {
    __shared__ float Ws[128*49];
    __shared__ float Xs[16][68];
    __shared__ float sc[128], sh[128];
    const int b = blockIdx.x, j0 = blockIdx.y * 32, tid = threadIdx.x;
    const int jq = tid & 7, ocg = tid >> 3;
    {
        float s = bn[tid] * rsqrtf(bn[384+tid] + 1e-5f);
        sc[tid] = s; sh[tid] = bn[128+tid] - bn[256+tid]*s;
    }
    float acc[8][8];
    #pragma unroll
    for (int o = 0; o < 8; o++)
        #pragma unroll
        for (int d = 0; d < 8; d++) acc[o][d] = 0.f;
    const int base_in = 2*j0 - 1 - PAD;
    const float* xb = x + (size_t)b*IC*LIN;
    for (int ch = 0; ch < IC/16; ch++) {
        __syncthreads();
        for (int i = tid; i < 128*48; i += 128) {
            int o = i / 48, u = i - o*48;
            Ws[o*49+u] = w[o*(IC*3) + ch*48 + u];
        }
        for (int i = tid; i < 16*66; i += 128) {
            int r = i / 66, c = i - r*66, gi = base_in + c;
            Xs[r][c] = (gi >= 0 && gi < LIN) ? xb[(ch*16+r)*LIN + gi] : 0.f;
        }
        __syncthreads();
        #pragma unroll
        for (int icl = 0; icl < 16; icl++) {
            float xv[10];
            const float2* xp = (const float2*)&Xs[icl][8*jq];
            #pragma unroll
            for (int i2 = 0; i2 < 5; i2++) { float2 t = xp[i2]; xv[2*i2] = t.x; xv[2*i2+1] = t.y; }
            #pragma unroll
            for (int o = 0; o < 8; o++) {
                const float* wr = &Ws[(ocg*8+o)*49 + icl*3];
                float w0 = wr[0], w1 = wr[1], w2 = wr[2];
                #pragma unroll
                for (int d = 0; d < 8; d++)
                    acc[o][d] = fmaf(w2, xv[d+2], fmaf(w1, xv[d+1], fmaf(w0, xv[d], acc[o][d])));
            }
        }
    }
    #pragma unroll
    for (int o = 0; o < 8; o++) {
        int oc = ocg*8 + o;
        float s = sc[oc], h = sh[oc];
        #pragma unroll
        for (int dd = 0; dd < 4; dd++) {
            int j = j0 + 4*jq + dd;
            if (j < JOUT) {
                float r0 = fmaxf(fmaf(acc[o][2*dd],   s, h), 0.f);
                float r1 = fmaxf(fmaf(acc[o][2*dd+1], s, h), 0.f);
                out[((size_t)b*128+oc)*JOUT + j] = (j == 0) ? r1 : fmaxf(r0, r1);
            }
        }
    }
}

// ---------- map2 GEMM: [768,24448]x[24448,256], split-K=4 ----------
__global__ __launch_bounds__(256)
void k_map2(const float* __restrict__ A, const float* __restrict__ Bw, float* __restrict__ P) {
    __shared__ float As[16][64];
    __shared__ float Bs[16][64];
    const int m0 = blockIdx.x * 64, n0 = blockIdx.y * 64, k0 = blockIdx.z * 6112;
    const int tid = threadIdx.x, tm = tid >> 4, tn = tid & 15;
    float acc[4][4];
    #pragma unroll
    for (int i = 0; i < 4; i++)
        #pragma unroll
        for (int j = 0; j < 4; j++) acc[i][j] = 0.f;
    const int ra = tid >> 2, ca = (tid & 3) * 4;
    const int rb = tid >> 4, cb4 = (tid & 15) * 4;
    for (int kc = k0; kc < k0 + 6112; kc += 16) {
        __syncthreads();
        float4 av = *(const float4*)&A[(size_t)(m0+ra)*24448 + kc + ca];
        As[ca][ra] = av.x; As[ca+1][ra] = av.y; As[ca+2][ra] = av.z; As[ca+3][ra] = av.w;
        *(float4*)&Bs[rb][cb4] = *(const float4*)&Bw[(size_t)(kc+rb)*256 + n0 + cb4];
        __syncthreads();
        #pragma unroll
        for (int kk = 0; kk < 16; kk++) {
            float4 a4 = *(const float4*)&As[kk][tm*4];
            float4 b4 = *(const float4*)&Bs[kk][tn*4];
            float av2[4] = {a4.x, a4.y, a4.z, a4.w}, bv[4] = {b4.x, b4.y, b4.z, b4.w};
            #pragma unroll
            for (int i = 0; i < 4; i++)
                #pragma unroll
                for (int j = 0; j < 4; j++) acc[i][j] = fmaf(av2[i], bv[j], acc[i][j]);
        }
    }
    #pragma unroll
    for (int i = 0; i < 4; i++)
        *(float4*)&P[(size_t)(blockIdx.z*768 + m0 + tm*4 + i)*256 + n0 + tn*4] =
            make_float4(acc[i][0], acc[i][1], acc[i][2], acc[i][3]);
}

// ---------- split-K combine + bias + BN + positional encoding ----------
__global__ void k_combine(const float* __restrict__ mp, const float* __restrict__ mb,
                          const float* __restrict__ bnm, float* __restrict__ a) {
    const int row = blockIdx.x, f = threadIdx.x;
    float s = mp[row*256+f] + mp[(768+row)*256+f] + mp[(2*768+row)*256+f] + mp[(3*768+row)*256+f] + mb[f];
    s = fmaf(s - bnm[512+f], bnm[f] * rsqrtf(bnm[768+f] + 1e-5f), bnm[256+f]);
    const int t = (row >> 2) % 6;
    const float div = expf((float)((f >> 1) * 2) * (-4.605170185988091f / 256.f));
    const float ang = (float)t * div;
    a[row*256+f] = s + ((f & 1) ? cosf(ang) : sinf(ang));
}

// ---------- f = Xc @ Gw + gb (per 8-node graph) ----------
__global__ void k_graphf(const float* __restrict__ a, const float* __restrict__ gw,
                         const float* __restrict__ gb, float* __restrict__ fout,
                         int nw, int stride) {
    const int g = blockIdx.x, bs = g / nw, j = g % nw, tid = threadIdx.x; // 256
    __shared__ float Xc[8][257];
    #pragma unroll
    for (int n = 0; n < 8; n++) {
        int row = (bs*6 + j*stride + (n>>2))*4 + (n&3);
        Xc[n][tid] = a[row*256 + tid];
    }
    __syncthreads();
    float acc[8], bias = gb[tid];
    #pragma unroll
    for (int n = 0; n < 8; n++) acc[n] = bias;
    for (int d = 0; d < 256; d++) {
        float wv = gw[d*256 + tid];
        #pragma unroll
        for (int n = 0; n < 8; n++) acc[n] = fmaf(Xc[n][d], wv, acc[n]);
    }
    #pragma unroll
    for (int n = 0; n < 8; n++) fout[(g*8+n)*256 + tid] = acc[n];
}

// ---------- adjacency: dot + leaky(-diag 1e8) + softmax + eye + decay mask ----------
__global__ void k_adj(const float* __restrict__ f, float* __restrict__ adj) {
    const int g = blockIdx.x, tid = threadIdx.x; // 64
    __shared__ float fs[8][257];
    for (int i = tid; i < 2048; i += 64) fs[i>>8][i&255] = f[g*2048 + i];
    __syncthreads();
    const int n = tid >> 3, m = tid & 7;
    float dot = 0.f;
    for (int d = 0; d < 256; d++) dot = fmaf(fs[n][d], fs[m][d], dot);
    if (n == m) dot -= 1e8f;
    float v = dot > 0.f ? dot : 0.01f*dot;
    float mx = v;
    #pragma unroll
    for (int o = 1; o < 8; o <<= 1) mx = fmaxf(mx, __shfl_xor_sync(0xffffffffu, mx, o, 8));
    float e = expf(v - mx), s = e;
    #pragma unroll
    for (int o = 1; o < 8; o <<= 1) s += __shfl_xor_sync(0xffffffffu, s, o, 8);
    float av = e / s;
    if (n == m) av += 1.f;
    adj[g*64 + tid] = av * (((n>>2) == (m>>2)) ? 1.f : 0.7f);
}

// ---------- MPNN: (Adj @ BN(Xc)) @ Tw + tb; BN + leaky; mean pool; scatter to feats ----------
__global__ __launch_bounds__(128)
void k_mpnn(const float* __restrict__ a, const float* __restrict__ adj,
            const float* __restrict__ bnA, const float* __restrict__ tw,
            const float* __restrict__ tb, const float* __restrict__ bnM,
            float* __restrict__ feats, int nw, int stride, int off) {
    const int g = blockIdx.x, bs = g / nw, j = g % nw, tid = threadIdx.x; // 128
    __shared__ float Xb[8][257];
    __shared__ float Ys[8][257];
    __shared__ float Aj[64];
    if (tid < 64) Aj[tid] = adj[g*64 + tid];
    #pragma unroll
    for (int h = 0; h < 2; h++) {
        int d = tid + 128*h;
        float s = bnA[d] * rsqrtf(bnA[768+d] + 1e-5f);
        float sh = bnA[256+d] - bnA[512+d]*s;
        #pragma unroll
        for (int n = 0; n < 8; n++) {
            int row = (bs*6 + j*stride + (n>>2))*4 + (n&3);
            Xb[n][d] = fmaf(a[row*256+d], s, sh);
        }
    }
    __syncthreads();
    #pragma unroll
    for (int h = 0; h < 2; h++) {
        int d = tid + 128*h;
        #pragma unroll
        for (int n = 0; n < 8; n++) {
            float acc = 0.f;
            #pragma unroll
            for (int m = 0; m < 8; m++) acc = fmaf(Aj[n*8+m], Xb[m][d], acc);
            Ys[n][d] = acc;
        }
    }
    __syncthreads();
    float acc[8], bias = tb[tid];
    #pragma unroll
    for (int n = 0; n < 8; n++) acc[n] = bias;
    for (int d = 0; d < 256; d++) {
        float wv = tw[d*128 + tid];
        #pragma unroll
        for (int n = 0; n < 8; n++) acc[n] = fmaf(Ys[n][d], wv, acc[n]);
    }
    float s = bnM[tid] * rsqrtf(bnM[384+tid] + 1e-5f);
    float sh = bnM[128+tid] - bnM[256+tid]*s;
    #pragma unroll
    for (int n = 0; n < 8; n++) {
        float z = fmaf(acc[n], s, sh);
        acc[n] = z > 0.f ? z : 0.01f*z;
    }
    #pragma unroll
    for (int ns = 0; ns < 4; ns++)
        feats[bs*4096 + off + (j*4+ns)*128 + tid] = 0.5f*(acc[ns] + acc[4+ns]);
}

// ---------- FC layers ----------
template<int IN, int OUT, bool RELU>
__global__ void k_fc(const float* __restrict__ x, const float* __restrict__ w,
                     const float* __restrict__ b, float* __restrict__ y) {
    __shared__ float xs[IN];
    const int row = blockIdx.x, tid = threadIdx.x; // 128
    for (int i = tid; i < IN; i += 128) xs[i] = x[row*IN + i];
    __syncthreads();
    for (int o = tid; o < OUT; o += 128) {
        float acc = b[o];
        for (int k = 0; k < IN; k++) acc = fmaf(xs[k], w[k*OUT + o], acc);
        if (RELU) acc = fmaxf(acc, 0.f);
        y[row*OUT + o] = acc;
    }
}

extern "C" void kernel_launch(void* const* d_in, const int* in_sizes, int n_in,
                              void* d_out, int out_size) {
    const float* X       = (const float*)d_in[0];
    const float* conv1_w = (const float*)d_in[1];
    const float* bn1     = (const float*)d_in[2];
    const float* conv2_w = (const float*)d_in[3];
    const float* bn2     = (const float*)d_in[4];
    const float* conv3_w = (const float*)d_in[5];
    const float* bn3     = (const float*)d_in[6];
    const float* map2_w  = (const float*)d_in[7];
    const float* map2_b  = (const float*)d_in[8];
    const float* bn_map2 = (const float*)d_in[9];
    const float* g1_w = (const float*)d_in[10], *g1_b = (const float*)d_in[11], *bnA1 = (const float*)d_in[12];
    const float* th1_w = (const float*)d_in[13], *th1_b = (const float*)d_in[14], *bnM1 = (const float*)d_in[15];
    const float* g2_w = (const float*)d_in[16], *g2_b = (const float*)d_in[17], *bnA2 = (const float*)d_in[18];
    const float* th2_w = (const float*)d_in[19], *th2_b = (const float*)d_in[20], *bnM2 = (const float*)d_in[21];
    const float* fc1_w = (const float*)d_in[22], *fc1_b = (const float*)d_in[23];
    const float* fc2_w = (const float*)d_in[24], *fc2_b = (const float*)d_in[25];
    const float* fc3_w = (const float*)d_in[26], *fc3_b = (const float*)d_in[27];
    const float* fc4_w = (const float*)d_in[28], *fc4_b = (const float*)d_in[29];

    void* p;
    cudaGetSymbolAddress(&p, g_s1);   float* s1 = (float*)p;
    cudaGetSymbolAddress(&p, g_s2);   float* s2 = (float*)p;
    cudaGetSymbolAddress(&p, g_s3);   float* s3 = (float*)p;
    cudaGetSymbolAddress(&p, g_mp);   float* mp = (float*)p;
    cudaGetSymbolAddress(&p, g_a);    float* a  = (float*)p;
    cudaGetSymbolAddress(&p, g_f1);   float* f1 = (float*)p;
    cudaGetSymbolAddress(&p, g_f2);   float* f2 = (float*)p;
    cudaGetSymbolAddress(&p, g_adj1); float* adj1 = (float*)p;
    cudaGetSymbolAddress(&p, g_adj2); float* adj2 = (float*)p;
    cudaGetSymbolAddress(&p, g_feats);float* feats = (float*)p;
    cudaGetSymbolAddress(&p, g_t1);   float* t1 = (float*)p;
    cudaGetSymbolAddress(&p, g_t2);   float* t2 = (float*)p;
    cudaGetSymbolAddress(&p, g_t3);   float* t3 = (float*)p;

    k_conv1<<<dim3(768,3), 128>>>(X, conv1_w, bn1, s1);
    k_conv<64,2,751,377><<<dim3(768,12), 128>>>(s1, conv2_w, bn2, s2);
    k_conv<128,3,377,191><<<dim3(768,6), 128>>>(s2, conv3_w, bn3, s3);
    k_map2<<<dim3(12,4,4), 256>>>(s3, map2_w, mp);
    k_combine<<<768, 256>>>(mp, map2_b, bn_map2, a);
    k_graphf<<<160, 256>>>(a, g1_w, g1_b, f1, 5, 1);
    k_graphf<<<96, 256>>>(a, g2_w, g2_b, f2, 3, 2);
    k_adj<<<160, 64>>>(f1, adj1);
    k_adj<<<96, 64>>>(f2, adj2);
    k_mpnn<<<160, 128>>>(a, adj1, bnA1, th1_w, th1_b, bnM1, feats, 5, 1, 0);
    k_mpnn<<<96, 128>>>(a, adj2, bnA2, th2_w, th2_b, bnM2, feats, 3, 2, 2560);
    k_fc<4096,256,true><<<32, 128>>>(feats, fc1_w, fc1_b, t1);
    k_fc<256,256,true><<<32, 128>>>(t1, fc2_w, fc2_b, t2);
    k_fc<256,128,true><<<32, 128>>>(t2, fc3_w, fc3_b, t3);
    k_fc<128,5,false><<<32, 128>>>(t3, fc4_w, fc4_b, (float*)d_out);
}

// round 3
// speedup vs baseline: 1.2326x; 1.2326x over previous
#include <cuda_runtime.h>
#include <math.h>

// ---------- packed fp32x2 FMA (Blackwell FFMA2; 2x fp32 throughput) ----------
#define PACK2(d, lo, hi) asm("mov.b64 %0, {%1,%2};" : "=l"(d) : "f"(lo), "f"(hi))
#define FMA2(d, a, b, c) asm("fma.rn.f32x2 %0, %1, %2, %3;" : "=l"(d) : "l"(a), "l"(b), "l"(c))
#define UNPACK2(lo, hi, s) asm("mov.b64 {%0,%1}, %2;" : "=f"(lo), "=f"(hi) : "l"(s))

// ---------- scratch (device globals; no allocation allowed) ----------
__device__ float g_s1[768*64*751];
__device__ float g_s2[768*128*377];
__device__ float g_s3[768*128*191];
__device__ float g_mp[8*768*256];
__device__ float g_a [768*256];
__device__ float g_f1[160*8*256];
__device__ float g_f2[96*8*256];
__device__ float g_adj1[160*64];
__device__ float g_adj2[96*64];
__device__ float g_feats[32*4096];
__device__ float g_t1[32*256];
__device__ float g_t2[32*256];
__device__ float g_t3[32*128];

// ---------- conv1 (1->64,K=3,pad=1)+BN+ReLU+maxpool2(pad=1): x[768,1500]->out[768,64,751] ----------
__global__ void k_conv1(const float* __restrict__ x, const float* __restrict__ w,
                        const float* __restrict__ bn, float* __restrict__ out) {
    __shared__ float xs[516];
    __shared__ float ws[192];
    __shared__ float sc[64], sh[64];
    const int b = blockIdx.x, j0 = blockIdx.y * 256, tid = threadIdx.x;
    for (int i = tid; i < 192; i += 128) ws[i] = w[i];
    if (tid < 64) {
        float s = bn[tid] * rsqrtf(bn[192+tid] + 1e-5f);
        sc[tid] = s; sh[tid] = bn[64+tid] - bn[128+tid]*s;
    }
    const int base = 2*j0 - 2;
    for (int i = tid; i < 514; i += 128) {
        int gi = base + i;
        xs[i] = (gi >= 0 && gi < 1500) ? x[b*1500 + gi] : 0.f;
    }
    __syncthreads();
    const int j1 = j0 + 2*tid, j2 = j1 + 1;
    if (j1 > 750) return;
    float xv[6];
    #pragma unroll
    for (int i = 0; i < 6; i++) xv[i] = xs[4*tid + i];
    const int cb = 2*j1 - 1;
    const bool v0 = (cb >= 0), v1 = (cb + 1 < 1500), v3 = (cb + 3 < 1500);
    for (int oc = 0; oc < 64; oc++) {
        float w0 = ws[3*oc], w1 = ws[3*oc+1], w2 = ws[3*oc+2];
        float s = sc[oc], h = sh[oc], r[4];
        #pragma unroll
        for (int d = 0; d < 4; d++) {
            float t = fmaf(w2, xv[d+2], fmaf(w1, xv[d+1], w0*xv[d]));
            r[d] = fmaxf(fmaf(t, s, h), 0.f);
        }
        out[(b*64+oc)*751 + j1] = fmaxf(v0 ? r[0] : -1e30f, v1 ? r[1] : -1e30f);
        if (j2 <= 750)
            out[(b*64+oc)*751 + j2] = fmaxf(r[2], v3 ? r[3] : -1e30f);
    }
}

// ---------- generic conv (IC->128,K=3)+BN+ReLU+pool, FFMA2 over oc pairs ----------
// Block 128 thr = 16 ocGroups x 8 jGroups; thread tile: 4 oc-pairs x 8 conv pos.
template<int IC, int PAD, int LIN, int JOUT>
__global__ __launch_bounds__(128)
void k_conv(const float* __restrict__ x, const float* __restrict__ w,
            const float* __restrict__ bn, float* __restrict__ out) {
    __shared__ float Ws[48*130];      // [u = icl*3+tap][oc], pad 2 keeps 8B align
    __shared__ float Xs[16][68];
    __shared__ float sc[128], sh[128];
    const int b = blockIdx.x, j0 = blockIdx.y * 32, tid = threadIdx.x;
    const int jq = tid & 7, ocg = tid >> 3;
    {
        float s = bn[tid] * rsqrtf(bn[384+tid] + 1e-5f);
        sc[tid] = s; sh[tid] = bn[128+tid] - bn[256+tid]*s;
    }
    unsigned long long acc2[4][8];
    #pragma unroll
    for (int op = 0; op < 4; op++)
        #pragma unroll
        for (int d = 0; d < 8; d++) acc2[op][d] = 0ull;
    const int base_in = 2*j0 - 1 - PAD;
    const float* xb_ = x + (size_t)b*IC*LIN;
    for (int ch = 0; ch < IC/16; ch++) {
        __syncthreads();
        for (int i = tid; i < 128*48; i += 128) {
            int o = i / 48, u = i - o*48;
            Ws[u*130 + o] = w[o*(IC*3) + ch*48 + u];   // transposed store
        }
        for (int i = tid; i < 16*66; i += 128) {
            int r = i / 66, c = i - r*66, gi = base_in + c;
            Xs[r][c] = (gi >= 0 && gi < LIN) ? xb_[(ch*16+r)*LIN + gi] : 0.f;
        }
        __syncthreads();
        #pragma unroll
        for (int icl = 0; icl < 16; icl++) {
            float xv[10];
            const float2* xp = (const float2*)&Xs[icl][8*jq];
            #pragma unroll
            for (int i2 = 0; i2 < 5; i2++) { float2 t = xp[i2]; xv[2*i2] = t.x; xv[2*i2+1] = t.y; }
            unsigned long long xb2[10];
            #pragma unroll
            for (int k = 0; k < 10; k++) PACK2(xb2[k], xv[k], xv[k]);
            #pragma unroll
            for (int tap = 0; tap < 3; tap++) {
                const unsigned long long* wrow =
                    (const unsigned long long*)&Ws[(icl*3+tap)*130 + ocg*8];
                #pragma unroll
                for (int op = 0; op < 4; op++) {
                    unsigned long long wp = wrow[op];
                    #pragma unroll
                    for (int d = 0; d < 8; d++)
                        FMA2(acc2[op][d], wp, xb2[d+tap], acc2[op][d]);
                }
            }
        }
    }
    #pragma unroll
    for (int op = 0; op < 4; op++) {
        int oc0 = ocg*8 + 2*op;
        float v0[8], v1[8];
        #pragma unroll
        for (int d = 0; d < 8; d++) UNPACK2(v0[d], v1[d], acc2[op][d]);
        #pragma unroll
        for (int half = 0; half < 2; half++) {
            int oc = oc0 + half;
            const float* vv = half ? v1 : v0;
            float s = sc[oc], h = sh[oc];
            #pragma unroll
            for (int dd = 0; dd < 4; dd++) {
                int j = j0 + 4*jq + dd;
                if (j < JOUT) {
                    float r0 = fmaxf(fmaf(vv[2*dd],   s, h), 0.f);
                    float r1 = fmaxf(fmaf(vv[2*dd+1], s, h), 0.f);
                    out[((size_t)b*128+oc)*JOUT + j] = (j == 0) ? r1 : fmaxf(r0, r1);
                }
            }
        }
    }
}

// ---------- map2 GEMM: [768,24448]x[24448,256], split-K=8, FFMA2 over N pairs ----------
__global__ __launch_bounds__(256)
void k_map2(const float* __restrict__ A, const float* __restrict__ Bw, float* __restrict__ P) {
    __shared__ float As[16][64];
    __shared__ float Bs[16][64];
    const int m0 = blockIdx.x * 64, n0 = blockIdx.y * 64, k0 = blockIdx.z * 3056;
    const int tid = threadIdx.x, tm = tid >> 4, tn = tid & 15;
    unsigned long long acc2[4][2];
    #pragma unroll
    for (int i = 0; i < 4; i++) { acc2[i][0] = 0ull; acc2[i][1] = 0ull; }
    const int ra = tid >> 2, ca = (tid & 3) * 4;
    const int rb = tid >> 4, cb4 = (tid & 15) * 4;
    for (int kc = k0; kc < k0 + 3056; kc += 16) {
        __syncthreads();
        float4 av = *(const float4*)&A[(size_t)(m0+ra)*24448 + kc + ca];
        As[ca][ra] = av.x; As[ca+1][ra] = av.y; As[ca+2][ra] = av.z; As[ca+3][ra] = av.w;
        *(float4*)&Bs[rb][cb4] = *(const float4*)&Bw[(size_t)(kc+rb)*256 + n0 + cb4];
        __syncthreads();
        #pragma unroll
        for (int kk = 0; kk < 16; kk++) {
            float4 a4 = *(const float4*)&As[kk][tm*4];
            ulonglong2 bp = *(const ulonglong2*)&Bs[kk][tn*4];
            unsigned long long ab[4];
            PACK2(ab[0], a4.x, a4.x); PACK2(ab[1], a4.y, a4.y);
            PACK2(ab[2], a4.z, a4.z); PACK2(ab[3], a4.w, a4.w);
            #pragma unroll
            for (int i = 0; i < 4; i++) {
                FMA2(acc2[i][0], ab[i], bp.x, acc2[i][0]);
                FMA2(acc2[i][1], ab[i], bp.y, acc2[i][1]);
            }
        }
    }
    #pragma unroll
    for (int i = 0; i < 4; i++) {
        float o0, o1, o2, o3;
        UNPACK2(o0, o1, acc2[i][0]);
        UNPACK2(o2, o3, acc2[i][1]);
        *(float4*)&P[(size_t)(blockIdx.z*768 + m0 + tm*4 + i)*256 + n0 + tn*4] =
            make_float4(o0, o1, o2, o3);
    }
}

// ---------- split-K combine + bias + BN + positional encoding ----------
__global__ void k_combine(const float* __restrict__ mp, const float* __restrict__ mb,
                          const float* __restrict__ bnm, float* __restrict__ a) {
    const int row = blockIdx.x, f = threadIdx.x;
    float s = 0.f;
    #pragma unroll
    for (int z = 0; z < 8; z++) s += mp[(z*768+row)*256+f];
    s += mb[f];
    s = fmaf(s - bnm[512+f], bnm[f] * rsqrtf(bnm[768+f] + 1e-5f), bnm[256+f]);
    const int t = (row >> 2) % 6;
    const float div = expf((float)((f >> 1) * 2) * (-4.605170185988091f / 256.f));
    const float ang = (float)t * div;
    a[row*256+f] = s + ((f & 1) ? cosf(ang) : sinf(ang));
}

// ---------- f = Xc @ Gw + gb (per 8-node graph) ----------
__global__ void k_graphf(const float* __restrict__ a, const float* __restrict__ gw,
                         const float* __restrict__ gb, float* __restrict__ fout,
                         int nw, int stride) {
    const int g = blockIdx.x, bs = g / nw, j = g % nw, tid = threadIdx.x; // 256
    __shared__ float Xc[8][257];
    #pragma unroll
    for (int n = 0; n < 8; n++) {
        int row = (bs*6 + j*stride + (n>>2))*4 + (n&3);
        Xc[n][tid] = a[row*256 + tid];
    }
    __syncthreads();
    float acc[8], bias = gb[tid];
    #pragma unroll
    for (int n = 0; n < 8; n++) acc[n] = bias;
    for (int d = 0; d < 256; d++) {
        float wv = gw[d*256 + tid];
        #pragma unroll
        for (int n = 0; n < 8; n++) acc[n] = fmaf(Xc[n][d], wv, acc[n]);
    }
    #pragma unroll
    for (int n = 0; n < 8; n++) fout[(g*8+n)*256 + tid] = acc[n];
}

// ---------- adjacency ----------
__global__ void k_adj(const float* __restrict__ f, float* __restrict__ adj) {
    const int g = blockIdx.x, tid = threadIdx.x; // 64
    __shared__ float fs[8][257];
    for (int i = tid; i < 2048; i += 64) fs[i>>8][i&255] = f[g*2048 + i];
    __syncthreads();
    const int n = tid >> 3, m = tid & 7;
    float dot = 0.f;
    for (int d = 0; d < 256; d++) dot = fmaf(fs[n][d], fs[m][d], dot);
    if (n == m) dot -= 1e8f;
    float v = dot > 0.f ? dot : 0.01f*dot;
    float mx = v;
    #pragma unroll
    for (int o = 1; o < 8; o <<= 1) mx = fmaxf(mx, __shfl_xor_sync(0xffffffffu, mx, o, 8));
    float e = expf(v - mx), s = e;
    #pragma unroll
    for (int o = 1; o < 8; o <<= 1) s += __shfl_xor_sync(0xffffffffu, s, o, 8);
    float av = e / s;
    if (n == m) av += 1.f;
    adj[g*64 + tid] = av * (((n>>2) == (m>>2)) ? 1.f : 0.7f);
}

// ---------- MPNN ----------
__global__ __launch_bounds__(128)
void k_mpnn(const float* __restrict__ a, const float* __restrict__ adj,
            const float* __restrict__ bnA, const float* __restrict__ tw,
            const float* __restrict__ tb, const float* __restrict__ bnM,
            float* __restrict__ feats, int nw, int stride, int off) {
    const int g = blockIdx.x, bs = g / nw, j = g % nw, tid = threadIdx.x; // 128
    __shared__ float Xb[8][257];
    __shared__ float Ys[8][257];
    __shared__ float Aj[64];
    if (tid < 64) Aj[tid] = adj[g*64 + tid];
    #pragma unroll
    for (int h = 0; h < 2; h++) {
        int d = tid + 128*h;
        float s = bnA[d] * rsqrtf(bnA[768+d] + 1e-5f);
        float sh = bnA[256+d] - bnA[512+d]*s;
        #pragma unroll
        for (int n = 0; n < 8; n++) {
            int row = (bs*6 + j*stride + (n>>2))*4 + (n&3);
            Xb[n][d] = fmaf(a[row*256+d], s, sh);
        }
    }
    __syncthreads();
    #pragma unroll
    for (int h = 0; h < 2; h++) {
        int d = tid + 128*h;
        #pragma unroll
        for (int n = 0; n < 8; n++) {
            float acc = 0.f;
            #pragma unroll
            for (int m = 0; m < 8; m++) acc = fmaf(Aj[n*8+m], Xb[m][d], acc);
            Ys[n][d] = acc;
        }
    }
    __syncthreads();
    float acc[8], bias = tb[tid];
    #pragma unroll
    for (int n = 0; n < 8; n++) acc[n] = bias;
    for (int d = 0; d < 256; d++) {
        float wv = tw[d*128 + tid];
        #pragma unroll
        for (int n = 0; n < 8; n++) acc[n] = fmaf(Ys[n][d], wv, acc[n]);
    }
    float s = bnM[tid] * rsqrtf(bnM[384+tid] + 1e-5f);
    float sh = bnM[128+tid] - bnM[256+tid]*s;
    #pragma unroll
    for (int n = 0; n < 8; n++) {
        float z = fmaf(acc[n], s, sh);
        acc[n] = z > 0.f ? z : 0.01f*z;
    }
    #pragma unroll
    for (int ns = 0; ns < 4; ns++)
        feats[bs*4096 + off + (j*4+ns)*128 + tid] = 0.5f*(acc[ns] + acc[4+ns]);
}

// ---------- FC layers ----------
template<int IN, int OUT, bool RELU>
__global__ void k_fc(const float* __restrict__ x, const float* __restrict__ w,
                     const float* __restrict__ b, float* __restrict__ y) {
    __shared__ float xs[IN];
    const int row = blockIdx.x, tid = threadIdx.x; // 128
    for (int i = tid; i < IN; i += 128) xs[i] = x[row*IN + i];
    __syncthreads();
    for (int o = tid; o < OUT; o += 128) {
        float acc = b[o];
        for (int k = 0; k < IN; k++) acc = fmaf(xs[k], w[k*OUT + o], acc);
        if (RELU) acc = fmaxf(acc, 0.f);
        y[row*OUT + o] = acc;
    }
}

extern "C" void kernel_launch(void* const* d_in, const int* in_sizes, int n_in,
                              void* d_out, int out_size) {
    const float* X       = (const float*)d_in[0];
    const float* conv1_w = (const float*)d_in[1];
    const float* bn1     = (const float*)d_in[2];
    const float* conv2_w = (const float*)d_in[3];
    const float* bn2     = (const float*)d_in[4];
    const float* conv3_w = (const float*)d_in[5];
    const float* bn3     = (const float*)d_in[6];
    const float* map2_w  = (const float*)d_in[7];
    const float* map2_b  = (const float*)d_in[8];
    const float* bn_map2 = (const float*)d_in[9];
    const float* g1_w = (const float*)d_in[10], *g1_b = (const float*)d_in[11], *bnA1 = (const float*)d_in[12];
    const float* th1_w = (const float*)d_in[13], *th1_b = (const float*)d_in[14], *bnM1 = (const float*)d_in[15];
    const float* g2_w = (const float*)d_in[16], *g2_b = (const float*)d_in[17], *bnA2 = (const float*)d_in[18];
    const float* th2_w = (const float*)d_in[19], *th2_b = (const float*)d_in[20], *bnM2 = (const float*)d_in[21];
    const float* fc1_w = (const float*)d_in[22], *fc1_b = (const float*)d_in[23];
    const float* fc2_w = (const float*)d_in[24], *fc2_b = (const float*)d_in[25];
    const float* fc3_w = (const float*)d_in[26], *fc3_b = (const float*)d_in[27];
    const float* fc4_w = (const float*)d_in[28], *fc4_b = (const float*)d_in[29];

    void* p;
    cudaGetSymbolAddress(&p, g_s1);   float* s1 = (float*)p;
    cudaGetSymbolAddress(&p, g_s2);   float* s2 = (float*)p;
    cudaGetSymbolAddress(&p, g_s3);   float* s3 = (float*)p;
    cudaGetSymbolAddress(&p, g_mp);   float* mp = (float*)p;
    cudaGetSymbolAddress(&p, g_a);    float* a  = (float*)p;
    cudaGetSymbolAddress(&p, g_f1);   float* f1 = (float*)p;
    cudaGetSymbolAddress(&p, g_f2);   float* f2 = (float*)p;
    cudaGetSymbolAddress(&p, g_adj1); float* adj1 = (float*)p;
    cudaGetSymbolAddress(&p, g_adj2); float* adj2 = (float*)p;
    cudaGetSymbolAddress(&p, g_feats);float* feats = (float*)p;
    cudaGetSymbolAddress(&p, g_t1);   float* t1 = (float*)p;
    cudaGetSymbolAddress(&p, g_t2);   float* t2 = (float*)p;
    cudaGetSymbolAddress(&p, g_t3);   float* t3 = (float*)p;

    k_conv1<<<dim3(768,3), 128>>>(X, conv1_w, bn1, s1);
    k_conv<64,2,751,377><<<dim3(768,12), 128>>>(s1, conv2_w, bn2, s2);
    k_conv<128,3,377,191><<<dim3(768,6), 128>>>(s2, conv3_w, bn3, s3);
    k_map2<<<dim3(12,4,8), 256>>>(s3, map2_w, mp);
    k_combine<<<768, 256>>>(mp, map2_b, bn_map2, a);
    k_graphf<<<160, 256>>>(a, g1_w, g1_b, f1, 5, 1);
    k_graphf<<<96, 256>>>(a, g2_w, g2_b, f2, 3, 2);
    k_adj<<<160, 64>>>(f1, adj1);
    k_adj<<<96, 64>>>(f2, adj2);
    k_mpnn<<<160, 128>>>(a, adj1, bnA1, th1_w, th1_b, bnM1, feats, 5, 1, 0);
    k_mpnn<<<96, 128>>>(a, adj2, bnA2, th2_w, th2_b, bnM2, feats, 3, 2, 2560);
    k_fc<4096,256,true><<<32, 128>>>(feats, fc1_w, fc1_b, t1);
    k_fc<256,256,true><<<32, 128>>>(t1, fc2_w, fc2_b, t2);
    k_fc<256,128,true><<<32, 128>>>(t2, fc3_w, fc3_b, t3);
    k_fc<128,5,false><<<32, 128>>>(t3, fc4_w, fc4_b, (float*)d_out);
}

// round 4
// speedup vs baseline: 1.5603x; 1.2659x over previous
#include <cuda_runtime.h>
#include <math.h>

// ---------- tf32 MMA helpers ----------
__device__ __forceinline__ unsigned f2tf(float x) {
    unsigned r; asm("cvt.rna.tf32.f32 %0, %1;" : "=r"(r) : "f"(x)); return r;
}
__device__ __forceinline__ void mma_tf32(float* d, const unsigned* a, const unsigned* b) {
    asm("mma.sync.aligned.m16n8k8.row.col.f32.tf32.tf32.f32 "
        "{%0,%1,%2,%3}, {%4,%5,%6,%7}, {%8,%9}, {%0,%1,%2,%3};"
        : "+f"(d[0]), "+f"(d[1]), "+f"(d[2]), "+f"(d[3])
        : "r"(a[0]), "r"(a[1]), "r"(a[2]), "r"(a[3]), "r"(b[0]), "r"(b[1]));
}

// ---------- scratch (device globals; no allocation allowed) ----------
__device__ float g_s1[768*64*751];
__device__ float g_s2[768*128*377];
__device__ float g_s3[768*128*191];
__device__ float g_mp[8*768*256];
__device__ float g_a [768*256];
__device__ float g_f1[160*8*256];
__device__ float g_f2[96*8*256];
__device__ float g_adj1[160*64];
__device__ float g_adj2[96*64];
__device__ float g_feats[32*4096];
__device__ float g_t1[32*256];
__device__ float g_t2[32*256];
__device__ float g_t3[32*128];

// ---------- conv1 (1->64,K=3,pad=1)+BN+ReLU+maxpool2(pad=1): x[768,1500]->out[768,64,751] ----------
__global__ void k_conv1(const float* __restrict__ x, const float* __restrict__ w,
                        const float* __restrict__ bn, float* __restrict__ out) {
    __shared__ float xs[516];
    __shared__ float ws[192];
    __shared__ float sc[64], sh[64];
    const int b = blockIdx.x, j0 = blockIdx.y * 256, tid = threadIdx.x;
    for (int i = tid; i < 192; i += 128) ws[i] = w[i];
    if (tid < 64) {
        float s = bn[tid] * rsqrtf(bn[192+tid] + 1e-5f);
        sc[tid] = s; sh[tid] = bn[64+tid] - bn[128+tid]*s;
    }
    const int base = 2*j0 - 2;
    for (int i = tid; i < 514; i += 128) {
        int gi = base + i;
        xs[i] = (gi >= 0 && gi < 1500) ? x[b*1500 + gi] : 0.f;
    }
    __syncthreads();
    const int j1 = j0 + 2*tid, j2 = j1 + 1;
    if (j1 > 750) return;
    float xv[6];
    #pragma unroll
    for (int i = 0; i < 6; i++) xv[i] = xs[4*tid + i];
    const int cb = 2*j1 - 1;
    const bool v0 = (cb >= 0), v1 = (cb + 1 < 1500), v3 = (cb + 3 < 1500);
    for (int oc = 0; oc < 64; oc++) {
        float w0 = ws[3*oc], w1 = ws[3*oc+1], w2 = ws[3*oc+2];
        float s = sc[oc], h = sh[oc], r[4];
        #pragma unroll
        for (int d = 0; d < 4; d++) {
            float t = fmaf(w2, xv[d+2], fmaf(w1, xv[d+1], w0*xv[d]));
            r[d] = fmaxf(fmaf(t, s, h), 0.f);
        }
        out[(b*64+oc)*751 + j1] = fmaxf(v0 ? r[0] : -1e30f, v1 ? r[1] : -1e30f);
        if (j2 <= 750)
            out[(b*64+oc)*751 + j2] = fmaxf(r[2], v3 ? r[3] : -1e30f);
    }
}

// ---------- conv (IC->128,K=3)+BN+ReLU+pool via tf32 tensor-core implicit GEMM ----------
// Block 512 thr = 16 warps (4M x 4N); tile 128 oc x 256 conv positions (128 pooled).
// 3 taps = 3 shifted B-fragment reads of one shared X tile.
template<int IC, int PAD, int LIN, int JOUT>
__global__ __launch_bounds__(512)
void k_conv_mma(const float* __restrict__ x, const float* __restrict__ w,
                const float* __restrict__ bn, float* __restrict__ out) {
    __shared__ unsigned Wt[3][16][136];   // [tap][ic][oc] tf32
    __shared__ unsigned Xt[16][264];      // [ic][xcol] tf32 (258 used)
    __shared__ float sc[128], sh[128];
    const int b = blockIdx.x, p0 = blockIdx.y * 128;
    const int tid = threadIdx.x, lane = tid & 31, warp = tid >> 5;
    const int wm = warp & 3, wn = warp >> 2;
    if (tid < 128) {
        float s = bn[tid] * rsqrtf(bn[384+tid] + 1e-5f);
        sc[tid] = s; sh[tid] = bn[128+tid] - bn[256+tid]*s;
    }
    float c[2][8][4];
    #pragma unroll
    for (int mt = 0; mt < 2; mt++)
        #pragma unroll
        for (int nt = 0; nt < 8; nt++)
            #pragma unroll
            for (int q = 0; q < 4; q++) c[mt][nt][q] = 0.f;
    const int pc0 = 2*p0 - 1;           // first conv position of tile
    const int xbase = pc0 - PAD;        // first x index needed
    const float* xb = x + (size_t)b*IC*LIN;
    for (int ch = 0; ch < IC/16; ch++) {
        __syncthreads();
        for (int i = tid; i < 6144; i += 512) {        // weights: coalesced 48-runs
            int oc = i / 48, u = i % 48;
            Wt[u%3][u/3][oc] = f2tf(w[oc*(IC*3) + ch*48 + u]);
        }
        for (int i = tid; i < 16*258; i += 512) {
            int r = i / 258, cc = i % 258, gi = xbase + cc;
            Xt[r][cc] = f2tf((gi >= 0 && gi < LIN) ? xb[(ch*16+r)*LIN + gi] : 0.f);
        }
        __syncthreads();
        #pragma unroll
        for (int ks = 0; ks < 2; ks++) {
            const int kr = ks*8 + (lane & 3);
            #pragma unroll
            for (int t = 0; t < 3; t++) {
                unsigned a[2][4], bf[8][2];
                #pragma unroll
                for (int mt = 0; mt < 2; mt++) {
                    int om = wm*32 + mt*16 + (lane >> 2);
                    a[mt][0] = Wt[t][kr  ][om];
                    a[mt][1] = Wt[t][kr  ][om+8];
                    a[mt][2] = Wt[t][kr+4][om];
                    a[mt][3] = Wt[t][kr+4][om+8];
                }
                #pragma unroll
                for (int nt = 0; nt < 8; nt++) {
                    int cc = wn*64 + nt*8 + (lane >> 2) + t;
                    bf[nt][0] = Xt[kr  ][cc];
                    bf[nt][1] = Xt[kr+4][cc];
                }
                #pragma unroll
                for (int mt = 0; mt < 2; mt++)
                    #pragma unroll
                    for (int nt = 0; nt < 8; nt++)
                        mma_tf32(c[mt][nt], a[mt], bf[nt]);
            }
        }
    }
    // epilogue: BN + ReLU + pool(2,2,pad1). thread (c_even,c_odd) = one pooled output.
    #pragma unroll
    for (int mt = 0; mt < 2; mt++) {
        int ocr = wm*32 + mt*16 + (lane >> 2);
        #pragma unroll
        for (int nt = 0; nt < 8; nt++) {
            int lp = wn*64 + nt*8 + (lane & 3)*2;
            int j = p0 + (lp >> 1);
            if (j < JOUT) {
                #pragma unroll
                for (int rr = 0; rr < 2; rr++) {
                    int oc = ocr + rr*8;
                    float s = sc[oc], h = sh[oc];
                    float r0 = fmaxf(fmaf(c[mt][nt][rr*2],   s, h), 0.f);
                    float r1 = fmaxf(fmaf(c[mt][nt][rr*2+1], s, h), 0.f);
                    out[((size_t)b*128+oc)*JOUT + j] = (j == 0) ? r1 : fmaxf(r0, r1);
                }
            }
        }
    }
}

// ---------- map2 GEMM [768,24448]x[24448,256], tf32 MMA, split-K=8 ----------
__global__ __launch_bounds__(256)
void k_map2_mma(const float* __restrict__ A, const float* __restrict__ Bw, float* __restrict__ P) {
    __shared__ unsigned At[16][136];
    __shared__ unsigned Bt[16][72];
    const int m0 = blockIdx.x*128, n0 = blockIdx.y*64, k0 = blockIdx.z*3056;
    const int tid = threadIdx.x, lane = tid & 31, warp = tid >> 5;
    const int wm = warp & 3, wn = warp >> 2;
    float c[2][4][4];
    #pragma unroll
    for (int mt = 0; mt < 2; mt++)
        #pragma unroll
        for (int nt = 0; nt < 4; nt++)
            #pragma unroll
            for (int q = 0; q < 4; q++) c[mt][nt][q] = 0.f;
    for (int kc = k0; kc < k0 + 3056; kc += 16) {
        __syncthreads();
        #pragma unroll
        for (int s = 0; s < 2; s++) {
            int idx = tid + 256*s;
            int row = idx >> 2, kq = (idx & 3)*4;
            float4 v = *(const float4*)&A[(size_t)(m0+row)*24448 + kc + kq];
            At[kq  ][row] = f2tf(v.x); At[kq+1][row] = f2tf(v.y);
            At[kq+2][row] = f2tf(v.z); At[kq+3][row] = f2tf(v.w);
        }
        {
            int krow = tid >> 4, nq = (tid & 15)*4;
            float4 v = *(const float4*)&Bw[(size_t)(kc+krow)*256 + n0 + nq];
            Bt[krow][nq] = f2tf(v.x); Bt[krow][nq+1] = f2tf(v.y);
            Bt[krow][nq+2] = f2tf(v.z); Bt[krow][nq+3] = f2tf(v.w);
        }
        __syncthreads();
        #pragma unroll
        for (int ks = 0; ks < 2; ks++) {
            const int kr = ks*8 + (lane & 3);
            unsigned a[2][4], bf[4][2];
            #pragma unroll
            for (int mt = 0; mt < 2; mt++) {
                int om = wm*32 + mt*16 + (lane >> 2);
                a[mt][0] = At[kr  ][om];   a[mt][1] = At[kr  ][om+8];
                a[mt][2] = At[kr+4][om];   a[mt][3] = At[kr+4][om+8];
            }
            #pragma unroll
            for (int nt = 0; nt < 4; nt++) {
                int cc = wn*32 + nt*8 + (lane >> 2);
                bf[nt][0] = Bt[kr  ][cc];
                bf[nt][1] = Bt[kr+4][cc];
            }
            #pragma unroll
            for (int mt = 0; mt < 2; mt++)
                #pragma unroll
                for (int nt = 0; nt < 4; nt++)
                    mma_tf32(c[mt][nt], a[mt], bf[nt]);
        }
    }
    #pragma unroll
    for (int mt = 0; mt < 2; mt++) {
        int row = m0 + wm*32 + mt*16 + (lane >> 2);
        #pragma unroll
        for (int nt = 0; nt < 4; nt++) {
            int col = n0 + wn*32 + nt*8 + (lane & 3)*2;
            #pragma unroll
            for (int rr = 0; rr < 2; rr++)
                *(float2*)&P[(size_t)(blockIdx.z*768 + row + rr*8)*256 + col] =
                    make_float2(c[mt][nt][rr*2], c[mt][nt][rr*2+1]);
        }
    }
}

// ---------- split-K combine + bias + BN + positional encoding ----------
__global__ void k_combine(const float* __restrict__ mp, const float* __restrict__ mb,
                          const float* __restrict__ bnm, float* __restrict__ a) {
    const int row = blockIdx.x, f = threadIdx.x;
    float s = 0.f;
    #pragma unroll
    for (int z = 0; z < 8; z++) s += mp[(z*768+row)*256+f];
    s += mb[f];
    s = fmaf(s - bnm[512+f], bnm[f] * rsqrtf(bnm[768+f] + 1e-5f), bnm[256+f]);
    const int t = (row >> 2) % 6;
    const float div = expf((float)((f >> 1) * 2) * (-4.605170185988091f / 256.f));
    const float ang = (float)t * div;
    a[row*256+f] = s + ((f & 1) ? cosf(ang) : sinf(ang));
}

// ---------- f = Xc @ Gw + gb (per 8-node graph) ----------
__global__ void k_graphf(const float* __restrict__ a, const float* __restrict__ gw,
                         const float* __restrict__ gb, float* __restrict__ fout,
                         int nw, int stride) {
    const int g = blockIdx.x, bs = g / nw, j = g % nw, tid = threadIdx.x; // 256
    __shared__ float Xc[8][257];
    #pragma unroll
    for (int n = 0; n < 8; n++) {
        int row = (bs*6 + j*stride + (n>>2))*4 + (n&3);
        Xc[n][tid] = a[row*256 + tid];
    }
    __syncthreads();
    float acc[8], bias = gb[tid];
    #pragma unroll
    for (int n = 0; n < 8; n++) acc[n] = bias;
    for (int d = 0; d < 256; d++) {
        float wv = gw[d*256 + tid];
        #pragma unroll
        for (int n = 0; n < 8; n++) acc[n] = fmaf(Xc[n][d], wv, acc[n]);
    }
    #pragma unroll
    for (int n = 0; n < 8; n++) fout[(g*8+n)*256 + tid] = acc[n];
}

// ---------- adjacency ----------
__global__ void k_adj(const float* __restrict__ f, float* __restrict__ adj) {
    const int g = blockIdx.x, tid = threadIdx.x; // 64
    __shared__ float fs[8][257];
    for (int i = tid; i < 2048; i += 64) fs[i>>8][i&255] = f[g*2048 + i];
    __syncthreads();
    const int n = tid >> 3, m = tid & 7;
    float dot = 0.f;
    for (int d = 0; d < 256; d++) dot = fmaf(fs[n][d], fs[m][d], dot);
    if (n == m) dot -= 1e8f;
    float v = dot > 0.f ? dot : 0.01f*dot;
    float mx = v;
    #pragma unroll
    for (int o = 1; o < 8; o <<= 1) mx = fmaxf(mx, __shfl_xor_sync(0xffffffffu, mx, o, 8));
    float e = expf(v - mx), s = e;
    #pragma unroll
    for (int o = 1; o < 8; o <<= 1) s += __shfl_xor_sync(0xffffffffu, s, o, 8);
    float av = e / s;
    if (n == m) av += 1.f;
    adj[g*64 + tid] = av * (((n>>2) == (m>>2)) ? 1.f : 0.7f);
}

// ---------- MPNN ----------
__global__ __launch_bounds__(128)
void k_mpnn(const float* __restrict__ a, const float* __restrict__ adj,
            const float* __restrict__ bnA, const float* __restrict__ tw,
            const float* __restrict__ tb, const float* __restrict__ bnM,
            float* __restrict__ feats, int nw, int stride, int off) {
    const int g = blockIdx.x, bs = g / nw, j = g % nw, tid = threadIdx.x; // 128
    __shared__ float Xb[8][257];
    __shared__ float Ys[8][257];
    __shared__ float Aj[64];
    if (tid < 64) Aj[tid] = adj[g*64 + tid];
    #pragma unroll
    for (int h = 0; h < 2; h++) {
        int d = tid + 128*h;
        float s = bnA[d] * rsqrtf(bnA[768+d] + 1e-5f);
        float sh = bnA[256+d] - bnA[512+d]*s;
        #pragma unroll
        for (int n = 0; n < 8; n++) {
            int row = (bs*6 + j*stride + (n>>2))*4 + (n&3);
            Xb[n][d] = fmaf(a[row*256+d], s, sh);
        }
    }
    __syncthreads();
    #pragma unroll
    for (int h = 0; h < 2; h++) {
        int d = tid + 128*h;
        #pragma unroll
        for (int n = 0; n < 8; n++) {
            float acc = 0.f;
            #pragma unroll
            for (int m = 0; m < 8; m++) acc = fmaf(Aj[n*8+m], Xb[m][d], acc);
            Ys[n][d] = acc;
        }
    }
    __syncthreads();
    float acc[8], bias = tb[tid];
    #pragma unroll
    for (int n = 0; n < 8; n++) acc[n] = bias;
    for (int d = 0; d < 256; d++) {
        float wv = tw[d*128 + tid];
        #pragma unroll
        for (int n = 0; n < 8; n++) acc[n] = fmaf(Ys[n][d], wv, acc[n]);
    }
    float s = bnM[tid] * rsqrtf(bnM[384+tid] + 1e-5f);
    float sh = bnM[128+tid] - bnM[256+tid]*s;
    #pragma unroll
    for (int n = 0; n < 8; n++) {
        float z = fmaf(acc[n], s, sh);
        acc[n] = z > 0.f ? z : 0.01f*z;
    }
    #pragma unroll
    for (int ns = 0; ns < 4; ns++)
        feats[bs*4096 + off + (j*4+ns)*128 + tid] = 0.5f*(acc[ns] + acc[4+ns]);
}

// ---------- FC layers ----------
template<int IN, int OUT, bool RELU>
__global__ void k_fc(const float* __restrict__ x, const float* __restrict__ w,
                     const float* __restrict__ b, float* __restrict__ y) {
    __shared__ float xs[IN];
    const int row = blockIdx.x, tid = threadIdx.x; // 128
    for (int i = tid; i < IN; i += 128) xs[i] = x[row*IN + i];
    __syncthreads();
    for (int o = tid; o < OUT; o += 128) {
        float acc = b[o];
        for (int k = 0; k < IN; k++) acc = fmaf(xs[k], w[k*OUT + o], acc);
        if (RELU) acc = fmaxf(acc, 0.f);
        y[row*OUT + o] = acc;
    }
}

extern "C" void kernel_launch(void* const* d_in, const int* in_sizes, int n_in,
                              void* d_out, int out_size) {
    const float* X       = (const float*)d_in[0];
    const float* conv1_w = (const float*)d_in[1];
    const float* bn1     = (const float*)d_in[2];
    const float* conv2_w = (const float*)d_in[3];
    const float* bn2     = (const float*)d_in[4];
    const float* conv3_w = (const float*)d_in[5];
    const float* bn3     = (const float*)d_in[6];
    const float* map2_w  = (const float*)d_in[7];
    const float* map2_b  = (const float*)d_in[8];
    const float* bn_map2 = (const float*)d_in[9];
    const float* g1_w = (const float*)d_in[10], *g1_b = (const float*)d_in[11], *bnA1 = (const float*)d_in[12];
    const float* th1_w = (const float*)d_in[13], *th1_b = (const float*)d_in[14], *bnM1 = (const float*)d_in[15];
    const float* g2_w = (const float*)d_in[16], *g2_b = (const float*)d_in[17], *bnA2 = (const float*)d_in[18];
    const float* th2_w = (const float*)d_in[19], *th2_b = (const float*)d_in[20], *bnM2 = (const float*)d_in[21];
    const float* fc1_w = (const float*)d_in[22], *fc1_b = (const float*)d_in[23];
    const float* fc2_w = (const float*)d_in[24], *fc2_b = (const float*)d_in[25];
    const float* fc3_w = (const float*)d_in[26], *fc3_b = (const float*)d_in[27];
    const float* fc4_w = (const float*)d_in[28], *fc4_b = (const float*)d_in[29];

    void* p;
    cudaGetSymbolAddress(&p, g_s1);   float* s1 = (float*)p;
    cudaGetSymbolAddress(&p, g_s2);   float* s2 = (float*)p;
    cudaGetSymbolAddress(&p, g_s3);   float* s3 = (float*)p;
    cudaGetSymbolAddress(&p, g_mp);   float* mp = (float*)p;
    cudaGetSymbolAddress(&p, g_a);    float* a  = (float*)p;
    cudaGetSymbolAddress(&p, g_f1);   float* f1 = (float*)p;
    cudaGetSymbolAddress(&p, g_f2);   float* f2 = (float*)p;
    cudaGetSymbolAddress(&p, g_adj1); float* adj1 = (float*)p;
    cudaGetSymbolAddress(&p, g_adj2); float* adj2 = (float*)p;
    cudaGetSymbolAddress(&p, g_feats);float* feats = (float*)p;
    cudaGetSymbolAddress(&p, g_t1);   float* t1 = (float*)p;
    cudaGetSymbolAddress(&p, g_t2);   float* t2 = (float*)p;
    cudaGetSymbolAddress(&p, g_t3);   float* t3 = (float*)p;

    k_conv1<<<dim3(768,3), 128>>>(X, conv1_w, bn1, s1);
    k_conv_mma<64,2,751,377><<<dim3(768,3), 512>>>(s1, conv2_w, bn2, s2);
    k_conv_mma<128,3,377,191><<<dim3(768,2), 512>>>(s2, conv3_w, bn3, s3);
    k_map2_mma<<<dim3(6,4,8), 256>>>(s3, map2_w, mp);
    k_combine<<<768, 256>>>(mp, map2_b, bn_map2, a);
    k_graphf<<<160, 256>>>(a, g1_w, g1_b, f1, 5, 1);
    k_graphf<<<96, 256>>>(a, g2_w, g2_b, f2, 3, 2);
    k_adj<<<160, 64>>>(f1, adj1);
    k_adj<<<96, 64>>>(f2, adj2);
    k_mpnn<<<160, 128>>>(a, adj1, bnA1, th1_w, th1_b, bnM1, feats, 5, 1, 0);
    k_mpnn<<<96, 128>>>(a, adj2, bnA2, th2_w, th2_b, bnM2, feats, 3, 2, 2560);
    k_fc<4096,256,true><<<32, 128>>>(feats, fc1_w, fc1_b, t1);
    k_fc<256,256,true><<<32, 128>>>(t1, fc2_w, fc2_b, t2);
    k_fc<256,128,true><<<32, 128>>>(t2, fc3_w, fc3_b, t3);
    k_fc<128,5,false><<<32, 128>>>(t3, fc4_w, fc4_b, (float*)d_out);
}

// round 5
// speedup vs baseline: 1.9972x; 1.2800x over previous
#include <cuda_runtime.h>
#include <math.h>

// ---------- tf32 MMA (raw fp32 bits fed directly; HW truncates to tf32) ----------
__device__ __forceinline__ void mma_tf32(float* d, const unsigned* a, const unsigned* b) {
    asm("mma.sync.aligned.m16n8k8.row.col.f32.tf32.tf32.f32 "
        "{%0,%1,%2,%3}, {%4,%5,%6,%7}, {%8,%9}, {%0,%1,%2,%3};"
        : "+f"(d[0]), "+f"(d[1]), "+f"(d[2]), "+f"(d[3])
        : "r"(a[0]), "r"(a[1]), "r"(a[2]), "r"(a[3]), "r"(b[0]), "r"(b[1]));
}

// ---------- scratch (device globals; no allocation allowed) ----------
__device__ float g_s1[768*64*751];
__device__ float g_s2[768*128*377];
__device__ float g_s3[768*128*191];
__device__ float g_mp[16*768*256];
__device__ float g_a [768*256];
__device__ float g_f1[160*8*256];
__device__ float g_f2[96*8*256];
__device__ float g_adj1[160*64];
__device__ float g_adj2[96*64];
__device__ float g_feats[32*4096];
__device__ float g_t1[32*256];
__device__ float g_t2[32*256];
__device__ float g_t3[32*128];

// ---------- conv1 (1->64,K=3,pad=1)+BN+ReLU+maxpool2(pad=1) ----------
__global__ void k_conv1(const float* __restrict__ x, const float* __restrict__ w,
                        const float* __restrict__ bn, float* __restrict__ out) {
    __shared__ float xs[516];
    __shared__ float ws[192];
    __shared__ float sc[64], sh[64];
    const int b = blockIdx.x, j0 = blockIdx.y * 256, tid = threadIdx.x;
    for (int i = tid; i < 192; i += 128) ws[i] = w[i];
    if (tid < 64) {
        float s = bn[tid] * rsqrtf(bn[192+tid] + 1e-5f);
        sc[tid] = s; sh[tid] = bn[64+tid] - bn[128+tid]*s;
    }
    const int base = 2*j0 - 2;
    for (int i = tid; i < 514; i += 128) {
        int gi = base + i;
        xs[i] = (gi >= 0 && gi < 1500) ? x[b*1500 + gi] : 0.f;
    }
    __syncthreads();
    const int j1 = j0 + 2*tid, j2 = j1 + 1;
    if (j1 > 750) return;
    float xv[6];
    #pragma unroll
    for (int i = 0; i < 6; i++) xv[i] = xs[4*tid + i];
    const int cb = 2*j1 - 1;
    const bool v0 = (cb >= 0), v1 = (cb + 1 < 1500), v3 = (cb + 3 < 1500);
    for (int oc = 0; oc < 64; oc++) {
        float w0 = ws[3*oc], w1 = ws[3*oc+1], w2 = ws[3*oc+2];
        float s = sc[oc], h = sh[oc], r[4];
        #pragma unroll
        for (int d = 0; d < 4; d++) {
            float t = fmaf(w2, xv[d+2], fmaf(w1, xv[d+1], w0*xv[d]));
            r[d] = fmaxf(fmaf(t, s, h), 0.f);
        }
        out[(b*64+oc)*751 + j1] = fmaxf(v0 ? r[0] : -1e30f, v1 ? r[1] : -1e30f);
        if (j2 <= 750)
            out[(b*64+oc)*751 + j2] = fmaxf(r[2], v3 ? r[3] : -1e30f);
    }
}

// ---------- conv (IC->128,K=3)+BN+ReLU+pool via tf32 MMA ----------
// 512 thr = 16 warps (4wm x 4wn), warp tile 32oc x 32pos; block 128oc x 128 conv pos (64 pooled).
// 2 blocks/SM (launch_bounds) so one block's MMAs hide the other's fills.
template<int IC, int PAD, int LIN, int JOUT>
__global__ __launch_bounds__(512, 2)
void k_conv_mma(const float* __restrict__ x, const float* __restrict__ w,
                const float* __restrict__ bn, float* __restrict__ out) {
    __shared__ unsigned Wt[3][16][136];   // [tap][ic][oc] raw fp32 bits
    __shared__ unsigned Xt[16][136];      // [ic][xcol]
    __shared__ float sc[128], sh[128];
    const int b = blockIdx.x, p0 = blockIdx.y * 64;       // pooled base
    const int tid = threadIdx.x, lane = tid & 31, warp = tid >> 5;
    const int wm = warp & 3, wn = warp >> 2;
    const int grp = lane >> 2, tq = lane & 3;
    if (tid < 128) {
        float s = bn[tid] * rsqrtf(bn[384+tid] + 1e-5f);
        sc[tid] = s; sh[tid] = bn[128+tid] - bn[256+tid]*s;
    }
    float c[2][4][4];
    #pragma unroll
    for (int mt = 0; mt < 2; mt++)
        #pragma unroll
        for (int nt = 0; nt < 4; nt++)
            #pragma unroll
            for (int q = 0; q < 4; q++) c[mt][nt][q] = 0.f;
    const int xbase = 2*p0 - 1 - PAD;
    const float* xb = x + (size_t)b*IC*LIN;
    for (int ch = 0; ch < IC/16; ch++) {
        __syncthreads();
        for (int i = tid; i < 1536; i += 512) {           // weights via float4
            int oc = i / 12, q = i - oc*12;
            float4 v = *(const float4*)&w[oc*(IC*3) + ch*48 + q*4];
            int u = q*4;
            Wt[u%3][u/3][oc]             = __float_as_uint(v.x);
            Wt[(u+1)%3][(u+1)/3][oc]     = __float_as_uint(v.y);
            Wt[(u+2)%3][(u+2)/3][oc]     = __float_as_uint(v.z);
            Wt[(u+3)%3][(u+3)/3][oc]     = __float_as_uint(v.w);
        }
        for (int i = tid; i < 16*131; i += 512) {
            int r = i / 131, cc = i - r*131, gi = xbase + cc;
            Xt[r][cc] = __float_as_uint((gi >= 0 && gi < LIN) ? xb[(ch*16+r)*LIN + gi] : 0.f);
        }
        __syncthreads();
        #pragma unroll
        for (int ks = 0; ks < 2; ks++) {
            const int kr = ks*8 + tq;
            #pragma unroll
            for (int t = 0; t < 3; t++) {
                unsigned a[2][4], bf[4][2];
                #pragma unroll
                for (int mt = 0; mt < 2; mt++) {
                    int om = wm*32 + mt*16 + grp;
                    a[mt][0] = Wt[t][kr  ][om];
                    a[mt][1] = Wt[t][kr  ][om+8];
                    a[mt][2] = Wt[t][kr+4][om];
                    a[mt][3] = Wt[t][kr+4][om+8];
                }
                #pragma unroll
                for (int nt = 0; nt < 4; nt++) {
                    int cc = wn*32 + nt*8 + grp + t;
                    bf[nt][0] = Xt[kr  ][cc];
                    bf[nt][1] = Xt[kr+4][cc];
                }
                #pragma unroll
                for (int mt = 0; mt < 2; mt++)
                    #pragma unroll
                    for (int nt = 0; nt < 4; nt++)
                        mma_tf32(c[mt][nt], a[mt], bf[nt]);
            }
        }
    }
    #pragma unroll
    for (int mt = 0; mt < 2; mt++) {
        int ocr = wm*32 + mt*16 + grp;
        #pragma unroll
        for (int nt = 0; nt < 4; nt++) {
            int lp = wn*32 + nt*8 + tq*2;
            int j = p0 + (lp >> 1);
            if (j < JOUT) {
                #pragma unroll
                for (int rr = 0; rr < 2; rr++) {
                    int oc = ocr + rr*8;
                    float s = sc[oc], h = sh[oc];
                    float r0 = fmaxf(fmaf(c[mt][nt][rr*2],   s, h), 0.f);
                    float r1 = fmaxf(fmaf(c[mt][nt][rr*2+1], s, h), 0.f);
                    out[((size_t)b*128+oc)*JOUT + j] = (j == 0) ? r1 : fmaxf(r0, r1);
                }
            }
        }
    }
}

// ---------- map2 GEMM [768,24448]x[24448,256], tf32 MMA, split-K=16 (uneven tail) ----------
__global__ __launch_bounds__(128)
void k_map2_mma(const float* __restrict__ A, const float* __restrict__ Bw, float* __restrict__ P) {
    __shared__ unsigned At[16][72];
    __shared__ unsigned Bt[16][72];
    const int m0 = blockIdx.x*64, n0 = blockIdx.y*64;
    const int k0 = blockIdx.z*1536;
    const int kend = (k0 + 1536 < 24448) ? k0 + 1536 : 24448;
    const int tid = threadIdx.x, lane = tid & 31, warp = tid >> 5;
    const int wm = warp & 1, wn = warp >> 1;
    const int grp = lane >> 2, tq = lane & 3;
    float c[2][4][4];
    #pragma unroll
    for (int mt = 0; mt < 2; mt++)
        #pragma unroll
        for (int nt = 0; nt < 4; nt++)
            #pragma unroll
            for (int q = 0; q < 4; q++) c[mt][nt][q] = 0.f;
    for (int kc = k0; kc < kend; kc += 16) {
        __syncthreads();
        #pragma unroll
        for (int s = 0; s < 2; s++) {
            int idx = tid + 128*s;
            int row = idx >> 2, kq = (idx & 3)*4;
            float4 v = *(const float4*)&A[(size_t)(m0+row)*24448 + kc + kq];
            At[kq  ][row] = __float_as_uint(v.x); At[kq+1][row] = __float_as_uint(v.y);
            At[kq+2][row] = __float_as_uint(v.z); At[kq+3][row] = __float_as_uint(v.w);
        }
        #pragma unroll
        for (int s = 0; s < 2; s++) {
            int idx = tid + 128*s;
            int krow = idx >> 4, nq = (idx & 15)*4;
            float4 v = *(const float4*)&Bw[(size_t)(kc+krow)*256 + n0 + nq];
            Bt[krow][nq]   = __float_as_uint(v.x); Bt[krow][nq+1] = __float_as_uint(v.y);
            Bt[krow][nq+2] = __float_as_uint(v.z); Bt[krow][nq+3] = __float_as_uint(v.w);
        }
        __syncthreads();
        #pragma unroll
        for (int ks = 0; ks < 2; ks++) {
            const int kr = ks*8 + tq;
            unsigned a[2][4], bf[4][2];
            #pragma unroll
            for (int mt = 0; mt < 2; mt++) {
                int om = wm*32 + mt*16 + grp;
                a[mt][0] = At[kr  ][om];   a[mt][1] = At[kr  ][om+8];
                a[mt][2] = At[kr+4][om];   a[mt][3] = At[kr+4][om+8];
            }
            #pragma unroll
            for (int nt = 0; nt < 4; nt++) {
                int cc = wn*32 + nt*8 + grp;
                bf[nt][0] = Bt[kr  ][cc];
                bf[nt][1] = Bt[kr+4][cc];
            }
            #pragma unroll
            for (int mt = 0; mt < 2; mt++)
                #pragma unroll
                for (int nt = 0; nt < 4; nt++)
                    mma_tf32(c[mt][nt], a[mt], bf[nt]);
        }
    }
    #pragma unroll
    for (int mt = 0; mt < 2; mt++) {
        int row = m0 + wm*32 + mt*16 + grp;
        #pragma unroll
        for (int nt = 0; nt < 4; nt++) {
            int col = n0 + wn*32 + nt*8 + tq*2;
            #pragma unroll
            for (int rr = 0; rr < 2; rr++)
                *(float2*)&P[(size_t)(blockIdx.z*768 + row + rr*8)*256 + col] =
                    make_float2(c[mt][nt][rr*2], c[mt][nt][rr*2+1]);
        }
    }
}

// ---------- split-K combine + bias + BN + positional encoding ----------
__global__ void k_combine(const float* __restrict__ mp, const float* __restrict__ mb,
                          const float* __restrict__ bnm, float* __restrict__ a) {
    const int row = blockIdx.x, f = threadIdx.x;
    float s = 0.f;
    #pragma unroll
    for (int z = 0; z < 16; z++) s += mp[(z*768+row)*256+f];
    s += mb[f];
    s = fmaf(s - bnm[512+f], bnm[f] * rsqrtf(bnm[768+f] + 1e-5f), bnm[256+f]);
    const int t = (row >> 2) % 6;
    const float div = expf((float)((f >> 1) * 2) * (-4.605170185988091f / 256.f));
    const float ang = (float)t * div;
    a[row*256+f] = s + ((f & 1) ? cosf(ang) : sinf(ang));
}

// ---------- f = Xc @ Gw + gb (per 8-node graph) ----------
__global__ void k_graphf(const float* __restrict__ a, const float* __restrict__ gw,
                         const float* __restrict__ gb, float* __restrict__ fout,
                         int nw, int stride) {
    const int g = blockIdx.x, bs = g / nw, j = g % nw, tid = threadIdx.x; // 256
    __shared__ float Xc[8][257];
    #pragma unroll
    for (int n = 0; n < 8; n++) {
        int row = (bs*6 + j*stride + (n>>2))*4 + (n&3);
        Xc[n][tid] = a[row*256 + tid];
    }
    __syncthreads();
    float acc[8], bias = gb[tid];
    #pragma unroll
    for (int n = 0; n < 8; n++) acc[n] = bias;
    for (int d = 0; d < 256; d++) {
        float wv = gw[d*256 + tid];
        #pragma unroll
        for (int n = 0; n < 8; n++) acc[n] = fmaf(Xc[n][d], wv, acc[n]);
    }
    #pragma unroll
    for (int n = 0; n < 8; n++) fout[(g*8+n)*256 + tid] = acc[n];
}

// ---------- adjacency ----------
__global__ void k_adj(const float* __restrict__ f, float* __restrict__ adj) {
    const int g = blockIdx.x, tid = threadIdx.x; // 64
    __shared__ float fs[8][257];
    for (int i = tid; i < 2048; i += 64) fs[i>>8][i&255] = f[g*2048 + i];
    __syncthreads();
    const int n = tid >> 3, m = tid & 7;
    float dot = 0.f;
    for (int d = 0; d < 256; d++) dot = fmaf(fs[n][d], fs[m][d], dot);
    if (n == m) dot -= 1e8f;
    float v = dot > 0.f ? dot : 0.01f*dot;
    float mx = v;
    #pragma unroll
    for (int o = 1; o < 8; o <<= 1) mx = fmaxf(mx, __shfl_xor_sync(0xffffffffu, mx, o, 8));
    float e = expf(v - mx), s = e;
    #pragma unroll
    for (int o = 1; o < 8; o <<= 1) s += __shfl_xor_sync(0xffffffffu, s, o, 8);
    float av = e / s;
    if (n == m) av += 1.f;
    adj[g*64 + tid] = av * (((n>>2) == (m>>2)) ? 1.f : 0.7f);
}

// ---------- MPNN ----------
__global__ __launch_bounds__(128)
void k_mpnn(const float* __restrict__ a, const float* __restrict__ adj,
            const float* __restrict__ bnA, const float* __restrict__ tw,
            const float* __restrict__ tb, const float* __restrict__ bnM,
            float* __restrict__ feats, int nw, int stride, int off) {
    const int g = blockIdx.x, bs = g / nw, j = g % nw, tid = threadIdx.x; // 128
    __shared__ float Xb[8][257];
    __shared__ float Ys[8][257];
    __shared__ float Aj[64];
    if (tid < 64) Aj[tid] = adj[g*64 + tid];
    #pragma unroll
    for (int h = 0; h < 2; h++) {
        int d = tid + 128*h;
        float s = bnA[d] * rsqrtf(bnA[768+d] + 1e-5f);
        float sh = bnA[256+d] - bnA[512+d]*s;
        #pragma unroll
        for (int n = 0; n < 8; n++) {
            int row = (bs*6 + j*stride + (n>>2))*4 + (n&3);
            Xb[n][d] = fmaf(a[row*256+d], s, sh);
        }
    }
    __syncthreads();
    #pragma unroll
    for (int h = 0; h < 2; h++) {
        int d = tid + 128*h;
        #pragma unroll
        for (int n = 0; n < 8; n++) {
            float acc = 0.f;
            #pragma unroll
            for (int m = 0; m < 8; m++) acc = fmaf(Aj[n*8+m], Xb[m][d], acc);
            Ys[n][d] = acc;
        }
    }
    __syncthreads();
    float acc[8], bias = tb[tid];
    #pragma unroll
    for (int n = 0; n < 8; n++) acc[n] = bias;
    for (int d = 0; d < 256; d++) {
        float wv = tw[d*128 + tid];
        #pragma unroll
        for (int n = 0; n < 8; n++) acc[n] = fmaf(Ys[n][d], wv, acc[n]);
    }
    float s = bnM[tid] * rsqrtf(bnM[384+tid] + 1e-5f);
    float sh = bnM[128+tid] - bnM[256+tid]*s;
    #pragma unroll
    for (int n = 0; n < 8; n++) {
        float z = fmaf(acc[n], s, sh);
        acc[n] = z > 0.f ? z : 0.01f*z;
    }
    #pragma unroll
    for (int ns = 0; ns < 4; ns++)
        feats[bs*4096 + off + (j*4+ns)*128 + tid] = 0.5f*(acc[ns] + acc[4+ns]);
}

// ---------- FC layers ----------
template<int IN, int OUT, bool RELU>
__global__ void k_fc(const float* __restrict__ x, const float* __restrict__ w,
                     const float* __restrict__ b, float* __restrict__ y) {
    __shared__ float xs[IN];
    const int row = blockIdx.x, tid = threadIdx.x; // 128
    for (int i = tid; i < IN; i += 128) xs[i] = x[row*IN + i];
    __syncthreads();
    for (int o = tid; o < OUT; o += 128) {
        float acc = b[o];
        for (int k = 0; k < IN; k++) acc = fmaf(xs[k], w[k*OUT + o], acc);
        if (RELU) acc = fmaxf(acc, 0.f);
        y[row*OUT + o] = acc;
    }
}

extern "C" void kernel_launch(void* const* d_in, const int* in_sizes, int n_in,
                              void* d_out, int out_size) {
    const float* X       = (const float*)d_in[0];
    const float* conv1_w = (const float*)d_in[1];
    const float* bn1     = (const float*)d_in[2];
    const float* conv2_w = (const float*)d_in[3];
    const float* bn2     = (const float*)d_in[4];
    const float* conv3_w = (const float*)d_in[5];
    const float* bn3     = (const float*)d_in[6];
    const float* map2_w  = (const float*)d_in[7];
    const float* map2_b  = (const float*)d_in[8];
    const float* bn_map2 = (const float*)d_in[9];
    const float* g1_w = (const float*)d_in[10], *g1_b = (const float*)d_in[11], *bnA1 = (const float*)d_in[12];
    const float* th1_w = (const float*)d_in[13], *th1_b = (const float*)d_in[14], *bnM1 = (const float*)d_in[15];
    const float* g2_w = (const float*)d_in[16], *g2_b = (const float*)d_in[17], *bnA2 = (const float*)d_in[18];
    const float* th2_w = (const float*)d_in[19], *th2_b = (const float*)d_in[20], *bnM2 = (const float*)d_in[21];
    const float* fc1_w = (const float*)d_in[22], *fc1_b = (const float*)d_in[23];
    const float* fc2_w = (const float*)d_in[24], *fc2_b = (const float*)d_in[25];
    const float* fc3_w = (const float*)d_in[26], *fc3_b = (const float*)d_in[27];
    const float* fc4_w = (const float*)d_in[28], *fc4_b = (const float*)d_in[29];

    void* p;
    cudaGetSymbolAddress(&p, g_s1);   float* s1 = (float*)p;
    cudaGetSymbolAddress(&p, g_s2);   float* s2 = (float*)p;
    cudaGetSymbolAddress(&p, g_s3);   float* s3 = (float*)p;
    cudaGetSymbolAddress(&p, g_mp);   float* mp = (float*)p;
    cudaGetSymbolAddress(&p, g_a);    float* a  = (float*)p;
    cudaGetSymbolAddress(&p, g_f1);   float* f1 = (float*)p;
    cudaGetSymbolAddress(&p, g_f2);   float* f2 = (float*)p;
    cudaGetSymbolAddress(&p, g_adj1); float* adj1 = (float*)p;
    cudaGetSymbolAddress(&p, g_adj2); float* adj2 = (float*)p;
    cudaGetSymbolAddress(&p, g_feats);float* feats = (float*)p;
    cudaGetSymbolAddress(&p, g_t1);   float* t1 = (float*)p;
    cudaGetSymbolAddress(&p, g_t2);   float* t2 = (float*)p;
    cudaGetSymbolAddress(&p, g_t3);   float* t3 = (float*)p;

    k_conv1<<<dim3(768,3), 128>>>(X, conv1_w, bn1, s1);
    k_conv_mma<64,2,751,377><<<dim3(768,6), 512>>>(s1, conv2_w, bn2, s2);
    k_conv_mma<128,3,377,191><<<dim3(768,3), 512>>>(s2, conv3_w, bn3, s3);
    k_map2_mma<<<dim3(12,4,16), 128>>>(s3, map2_w, mp);
    k_combine<<<768, 256>>>(mp, map2_b, bn_map2, a);
    k_graphf<<<160, 256>>>(a, g1_w, g1_b, f1, 5, 1);
    k_graphf<<<96, 256>>>(a, g2_w, g2_b, f2, 3, 2);
    k_adj<<<160, 64>>>(f1, adj1);
    k_adj<<<96, 64>>>(f2, adj2);
    k_mpnn<<<160, 128>>>(a, adj1, bnA1, th1_w, th1_b, bnM1, feats, 5, 1, 0);
    k_mpnn<<<96, 128>>>(a, adj2, bnA2, th2_w, th2_b, bnM2, feats, 3, 2, 2560);
    k_fc<4096,256,true><<<32, 128>>>(feats, fc1_w, fc1_b, t1);
    k_fc<256,256,true><<<32, 128>>>(t1, fc2_w, fc2_b, t2);
    k_fc<256,128,true><<<32, 128>>>(t2, fc3_w, fc3_b, t3);
    k_fc<128,5,false><<<32, 128>>>(t3, fc4_w, fc4_b, (float*)d_out);
}

// round 6
// speedup vs baseline: 2.5850x; 1.2943x over previous
#include <cuda_runtime.h>
#include <math.h>

// ---------- tf32 MMA (raw fp32 bits; HW truncates to tf32) ----------
__device__ __forceinline__ void mma_tf32(float* d, const unsigned* a, const unsigned* b) {
    asm("mma.sync.aligned.m16n8k8.row.col.f32.tf32.tf32.f32 "
        "{%0,%1,%2,%3}, {%4,%5,%6,%7}, {%8,%9}, {%0,%1,%2,%3};"
        : "+f"(d[0]), "+f"(d[1]), "+f"(d[2]), "+f"(d[3])
        : "r"(a[0]), "r"(a[1]), "r"(a[2]), "r"(a[3]), "r"(b[0]), "r"(b[1]));
}
__device__ __forceinline__ void cpa16(void* dst, const void* src) {
    unsigned s = (unsigned)__cvta_generic_to_shared(dst);
    asm volatile("cp.async.cg.shared.global [%0], [%1], 16;" :: "r"(s), "l"(src));
}
__device__ __forceinline__ void cpa4(void* dst, const void* src) {
    unsigned s = (unsigned)__cvta_generic_to_shared(dst);
    asm volatile("cp.async.ca.shared.global [%0], [%1], 4;" :: "r"(s), "l"(src));
}
#define CP_COMMIT asm volatile("cp.async.commit_group;")
#define CP_WAIT1  asm volatile("cp.async.wait_group 1;")
#define CP_WAIT0  asm volatile("cp.async.wait_group 0;")

// ---------- scratch ----------
__device__ float g_s1[768*64*751];
__device__ float g_s2[768*128*377];
__device__ float g_s3[768*128*191];
__device__ float g_wt2[64*3*128];
__device__ float g_wt3[128*3*128];
__device__ float g_mp[16*768*256];
__device__ float g_a [768*256];
__device__ float g_f1[160*8*256];
__device__ float g_f2[96*8*256];
__device__ float g_adj1[160*64];
__device__ float g_adj2[96*64];
__device__ float g_feats[32*4096];
__device__ float g_t1[32*256];
__device__ float g_t2[32*256];
__device__ float g_t3[32*128];

// ---------- weight transpose: w[oc][ic][tap] -> wT[ch][tap][icl][oc] ----------
__global__ void k_wt(const float* __restrict__ w, float* __restrict__ wT, int IC) {
    int idx = blockIdx.x*256 + threadIdx.x;
    if (idx >= 128*IC*3) return;
    int oc = idx / (IC*3), r = idx - oc*(IC*3);
    int ic = r / 3, tap = r - ic*3;
    int ch = ic >> 4, icl = ic & 15;
    wT[ch*6144 + (tap*16+icl)*128 + oc] = w[idx];
}

// ---------- conv1 (1->64,K=3,pad=1)+BN+ReLU+maxpool2(pad=1) ----------
__global__ void k_conv1(const float* __restrict__ x, const float* __restrict__ w,
                        const float* __restrict__ bn, float* __restrict__ out) {
    __shared__ float xs[516];
    __shared__ float ws[192];
    __shared__ float sc[64], sh[64];
    const int b = blockIdx.x, j0 = blockIdx.y * 256, tid = threadIdx.x;
    for (int i = tid; i < 192; i += 128) ws[i] = w[i];
    if (tid < 64) {
        float s = bn[tid] * rsqrtf(bn[192+tid] + 1e-5f);
        sc[tid] = s; sh[tid] = bn[64+tid] - bn[128+tid]*s;
    }
    const int base = 2*j0 - 2;
    for (int i = tid; i < 514; i += 128) {
        int gi = base + i;
        xs[i] = (gi >= 0 && gi < 1500) ? x[b*1500 + gi] : 0.f;
    }
    __syncthreads();
    const int j1 = j0 + 2*tid, j2 = j1 + 1;
    if (j1 > 750) return;
    float xv[6];
    #pragma unroll
    for (int i = 0; i < 6; i++) xv[i] = xs[4*tid + i];
    const int cb = 2*j1 - 1;
    const bool v0 = (cb >= 0), v1 = (cb + 1 < 1500), v3 = (cb + 3 < 1500);
    for (int oc = 0; oc < 64; oc++) {
        float w0 = ws[3*oc], w1 = ws[3*oc+1], w2 = ws[3*oc+2];
        float s = sc[oc], h = sh[oc], r[4];
        #pragma unroll
        for (int d = 0; d < 4; d++) {
            float t = fmaf(w2, xv[d+2], fmaf(w1, xv[d+1], w0*xv[d]));
            r[d] = fmaxf(fmaf(t, s, h), 0.f);
        }
        out[(b*64+oc)*751 + j1] = fmaxf(v0 ? r[0] : -1e30f, v1 ? r[1] : -1e30f);
        if (j2 <= 750)
            out[(b*64+oc)*751 + j2] = fmaxf(r[2], v3 ? r[3] : -1e30f);
    }
}

// ---------- conv (IC->128,K=3)+BN+ReLU+pool via tf32 MMA, cp.async 2-stage pipeline ----------
template<int IC, int PAD, int LIN, int JOUT>
__global__ __launch_bounds__(512, 2)
void k_conv_mma(const float* __restrict__ x, const float* __restrict__ wT,
                const float* __restrict__ bn, float* __restrict__ out) {
    __shared__ unsigned Wt[2][48*136];    // [buf][tap*16+icl][oc] pad->136
    __shared__ unsigned Xt[2][16][136];   // [buf][icl][xcol]
    __shared__ float sc[128], sh[128];
    const int b = blockIdx.x, p0 = blockIdx.y * 64;
    const int tid = threadIdx.x, lane = tid & 31, warp = tid >> 5;
    const int wm = warp & 3, wn = warp >> 2;
    const int grp = lane >> 2, tq = lane & 3;
    if (tid < 128) {
        float s = bn[tid] * rsqrtf(bn[384+tid] + 1e-5f);
        sc[tid] = s; sh[tid] = bn[128+tid] - bn[256+tid]*s;
    }
    float c[2][4][4];
    #pragma unroll
    for (int mt = 0; mt < 2; mt++)
        #pragma unroll
        for (int nt = 0; nt < 4; nt++)
            #pragma unroll
            for (int q = 0; q < 4; q++) c[mt][nt][q] = 0.f;
    const int xbase = 2*p0 - 1 - PAD;
    const float* xb = x + (size_t)b*IC*LIN;
    const int NCH = IC/16;

    // stage loader
    auto stage = [&](int ch, int buf) {
        for (int i = tid; i < 1536; i += 512) {          // W: 48 rows x 32 float4
            int row = i >> 5, col4 = i & 31;
            cpa16(&Wt[buf][row*136 + col4*4], wT + (size_t)ch*6144 + row*128 + col4*4);
        }
        for (int i = tid; i < 16*132; i += 512) {        // X: 4B cp.async (odd strides)
            int r = i / 132, cc = i - r*132, gi = xbase + cc;
            if (gi >= 0 && gi < LIN) cpa4(&Xt[buf][r][cc], xb + (ch*16+r)*LIN + gi);
            else Xt[buf][r][cc] = 0u;
        }
        CP_COMMIT;
    };

    stage(0, 0);
    for (int ch = 0; ch < NCH; ch++) {
        bool more = (ch + 1 < NCH);
        if (more) stage(ch+1, (ch+1)&1);
        if (more) { CP_WAIT1; } else { CP_WAIT0; }
        __syncthreads();
        const int bq = ch & 1;
        #pragma unroll
        for (int ks = 0; ks < 2; ks++) {
            const int kr = ks*8 + tq;
            #pragma unroll
            for (int t = 0; t < 3; t++) {
                unsigned a[2][4], bf[4][2];
                #pragma unroll
                for (int mt = 0; mt < 2; mt++) {
                    int om = wm*32 + mt*16 + grp;
                    a[mt][0] = Wt[bq][(t*16+kr  )*136 + om];
                    a[mt][1] = Wt[bq][(t*16+kr  )*136 + om+8];
                    a[mt][2] = Wt[bq][(t*16+kr+4)*136 + om];
                    a[mt][3] = Wt[bq][(t*16+kr+4)*136 + om+8];
                }
                #pragma unroll
                for (int nt = 0; nt < 4; nt++) {
                    int cc = wn*32 + nt*8 + grp + t;
                    bf[nt][0] = Xt[bq][kr  ][cc];
                    bf[nt][1] = Xt[bq][kr+4][cc];
                }
                #pragma unroll
                for (int mt = 0; mt < 2; mt++)
                    #pragma unroll
                    for (int nt = 0; nt < 4; nt++)
                        mma_tf32(c[mt][nt], a[mt], bf[nt]);
            }
        }
        __syncthreads();
    }
    #pragma unroll
    for (int mt = 0; mt < 2; mt++) {
        int ocr = wm*32 + mt*16 + grp;
        #pragma unroll
        for (int nt = 0; nt < 4; nt++) {
            int lp = wn*32 + nt*8 + tq*2;
            int j = p0 + (lp >> 1);
            if (j < JOUT) {
                #pragma unroll
                for (int rr = 0; rr < 2; rr++) {
                    int oc = ocr + rr*8;
                    float s = sc[oc], h = sh[oc];
                    float r0 = fmaxf(fmaf(c[mt][nt][rr*2],   s, h), 0.f);
                    float r1 = fmaxf(fmaf(c[mt][nt][rr*2+1], s, h), 0.f);
                    out[((size_t)b*128+oc)*JOUT + j] = (j == 0) ? r1 : fmaxf(r0, r1);
                }
            }
        }
    }
}

// ---------- map2 GEMM [768,24448]x[24448,256], tf32 MMA, split-K=16, cp.async pipeline ----------
__global__ __launch_bounds__(256)
void k_map2_mma(const float* __restrict__ A, const float* __restrict__ Bw, float* __restrict__ P) {
    __shared__ unsigned At[2][64][36];   // [buf][m][k] KC=32 + pad4
    __shared__ unsigned Bt[2][32][72];   // [buf][k][n] 64 + pad8
    const int m0 = blockIdx.x*64, n0 = blockIdx.y*64;
    const int k0 = blockIdx.z*1536;
    const int kend = (k0 + 1536 < 24448) ? k0 + 1536 : 24448;
    const int niter = (kend - k0) >> 5;
    const int tid = threadIdx.x, lane = tid & 31, warp = tid >> 5;
    const int wm = warp & 3, wn = warp >> 2;
    const int grp = lane >> 2, tq = lane & 3;
    float c[4][4];
    #pragma unroll
    for (int nt = 0; nt < 4; nt++)
        #pragma unroll
        for (int q = 0; q < 4; q++) c[nt][q] = 0.f;

    auto stage = [&](int it, int buf) {
        int kc = k0 + it*32;
        #pragma unroll
        for (int s = 0; s < 2; s++) {
            int idx = tid + 256*s;
            int row = idx >> 3, c4 = idx & 7;
            cpa16(&At[buf][row][c4*4], &A[(size_t)(m0+row)*24448 + kc + c4*4]);
        }
        #pragma unroll
        for (int s = 0; s < 2; s++) {
            int idx = tid + 256*s;
            int row = idx >> 4, c4 = idx & 15;
            cpa16(&Bt[buf][row][c4*4], &Bw[(size_t)(kc+row)*256 + n0 + c4*4]);
        }
        CP_COMMIT;
    };

    stage(0, 0);
    for (int it = 0; it < niter; it++) {
        bool more = (it + 1 < niter);
        if (more) stage(it+1, (it+1)&1);
        if (more) { CP_WAIT1; } else { CP_WAIT0; }
        __syncthreads();
        const int bq = it & 1;
        #pragma unroll
        for (int ks = 0; ks < 4; ks++) {
            const int kr = ks*8 + tq;
            const int om = wm*16 + grp;
            unsigned a[4], bf[4][2];
            a[0] = At[bq][om  ][kr];   a[1] = At[bq][om+8][kr];
            a[2] = At[bq][om  ][kr+4]; a[3] = At[bq][om+8][kr+4];
            #pragma unroll
            for (int nt = 0; nt < 4; nt++) {
                int cc = wn*32 + nt*8 + grp;
                bf[nt][0] = Bt[bq][kr  ][cc];
                bf[nt][1] = Bt[bq][kr+4][cc];
            }
            #pragma unroll
            for (int nt = 0; nt < 4; nt++)
                mma_tf32(c[nt], a, bf[nt]);
        }
        __syncthreads();
    }
    {
        int row = m0 + wm*16 + grp;
        #pragma unroll
        for (int nt = 0; nt < 4; nt++) {
            int col = n0 + wn*32 + nt*8 + tq*2;
            *(float2*)&P[(size_t)(blockIdx.z*768 + row    )*256 + col] = make_float2(c[nt][0], c[nt][1]);
            *(float2*)&P[(size_t)(blockIdx.z*768 + row + 8)*256 + col] = make_float2(c[nt][2], c[nt][3]);
        }
    }
}

// ---------- split-K combine + bias + BN + positional encoding ----------
__global__ void k_combine(const float* __restrict__ mp, const float* __restrict__ mb,
                          const float* __restrict__ bnm, float* __restrict__ a) {
    const int row = blockIdx.x, f = threadIdx.x;
    float s = 0.f;
    #pragma unroll
    for (int z = 0; z < 16; z++) s += mp[(z*768+row)*256+f];
    s += mb[f];
    s = fmaf(s - bnm[512+f], bnm[f] * rsqrtf(bnm[768+f] + 1e-5f), bnm[256+f]);
    const int t = (row >> 2) % 6;
    const float div = expf((float)((f >> 1) * 2) * (-4.605170185988091f / 256.f));
    const float ang = (float)t * div;
    a[row*256+f] = s + ((f & 1) ? cosf(ang) : sinf(ang));
}

// ---------- f = Xc @ Gw + gb (per 8-node graph) ----------
__global__ void k_graphf(const float* __restrict__ a, const float* __restrict__ gw,
                         const float* __restrict__ gb, float* __restrict__ fout,
                         int nw, int stride) {
    const int g = blockIdx.x, bs = g / nw, j = g % nw, tid = threadIdx.x; // 256
    __shared__ float Xc[8][257];
    #pragma unroll
    for (int n = 0; n < 8; n++) {
        int row = (bs*6 + j*stride + (n>>2))*4 + (n&3);
        Xc[n][tid] = a[row*256 + tid];
    }
    __syncthreads();
    float acc[8], bias = gb[tid];
    #pragma unroll
    for (int n = 0; n < 8; n++) acc[n] = bias;
    for (int d = 0; d < 256; d++) {
        float wv = gw[d*256 + tid];
        #pragma unroll
        for (int n = 0; n < 8; n++) acc[n] = fmaf(Xc[n][d], wv, acc[n]);
    }
    #pragma unroll
    for (int n = 0; n < 8; n++) fout[(g*8+n)*256 + tid] = acc[n];
}

// ---------- adjacency ----------
__global__ void k_adj(const float* __restrict__ f, float* __restrict__ adj) {
    const int g = blockIdx.x, tid = threadIdx.x; // 64
    __shared__ float fs[8][257];
    for (int i = tid; i < 2048; i += 64) fs[i>>8][i&255] = f[g*2048 + i];
    __syncthreads();
    const int n = tid >> 3, m = tid & 7;
    float dot = 0.f;
    for (int d = 0; d < 256; d++) dot = fmaf(fs[n][d], fs[m][d], dot);
    if (n == m) dot -= 1e8f;
    float v = dot > 0.f ? dot : 0.01f*dot;
    float mx = v;
    #pragma unroll
    for (int o = 1; o < 8; o <<= 1) mx = fmaxf(mx, __shfl_xor_sync(0xffffffffu, mx, o, 8));
    float e = expf(v - mx), s = e;
    #pragma unroll
    for (int o = 1; o < 8; o <<= 1) s += __shfl_xor_sync(0xffffffffu, s, o, 8);
    float av = e / s;
    if (n == m) av += 1.f;
    adj[g*64 + tid] = av * (((n>>2) == (m>>2)) ? 1.f : 0.7f);
}

// ---------- MPNN ----------
__global__ __launch_bounds__(128)
void k_mpnn(const float* __restrict__ a, const float* __restrict__ adj,
            const float* __restrict__ bnA, const float* __restrict__ tw,
            const float* __restrict__ tb, const float* __restrict__ bnM,
            float* __restrict__ feats, int nw, int stride, int off) {
    const int g = blockIdx.x, bs = g / nw, j = g % nw, tid = threadIdx.x; // 128
    __shared__ float Xb[8][257];
    __shared__ float Ys[8][257];
    __shared__ float Aj[64];
    if (tid < 64) Aj[tid] = adj[g*64 + tid];
    #pragma unroll
    for (int h = 0; h < 2; h++) {
        int d = tid + 128*h;
        float s = bnA[d] * rsqrtf(bnA[768+d] + 1e-5f);
        float sh = bnA[256+d] - bnA[512+d]*s;
        #pragma unroll
        for (int n = 0; n < 8; n++) {
            int row = (bs*6 + j*stride + (n>>2))*4 + (n&3);
            Xb[n][d] = fmaf(a[row*256+d], s, sh);
        }
    }
    __syncthreads();
    #pragma unroll
    for (int h = 0; h < 2; h++) {
        int d = tid + 128*h;
        #pragma unroll
        for (int n = 0; n < 8; n++) {
            float acc = 0.f;
            #pragma unroll
            for (int m = 0; m < 8; m++) acc = fmaf(Aj[n*8+m], Xb[m][d], acc);
            Ys[n][d] = acc;
        }
    }
    __syncthreads();
    float acc[8], bias = tb[tid];
    #pragma unroll
    for (int n = 0; n < 8; n++) acc[n] = bias;
    for (int d = 0; d < 256; d++) {
        float wv = tw[d*128 + tid];
        #pragma unroll
        for (int n = 0; n < 8; n++) acc[n] = fmaf(Ys[n][d], wv, acc[n]);
    }
    float s = bnM[tid] * rsqrtf(bnM[384+tid] + 1e-5f);
    float sh = bnM[128+tid] - bnM[256+tid]*s;
    #pragma unroll
    for (int n = 0; n < 8; n++) {
        float z = fmaf(acc[n], s, sh);
        acc[n] = z > 0.f ? z : 0.01f*z;
    }
    #pragma unroll
    for (int ns = 0; ns < 4; ns++)
        feats[bs*4096 + off + (j*4+ns)*128 + tid] = 0.5f*(acc[ns] + acc[4+ns]);
}

// ---------- FC layers ----------
template<int IN, int OUT, bool RELU>
__global__ void k_fc(const float* __restrict__ x, const float* __restrict__ w,
                     const float* __restrict__ b, float* __restrict__ y) {
    __shared__ float xs[IN];
    const int row = blockIdx.x, tid = threadIdx.x; // 128
    for (int i = tid; i < IN; i += 128) xs[i] = x[row*IN + i];
    __syncthreads();
    for (int o = tid; o < OUT; o += 128) {
        float acc = b[o];
        for (int k = 0; k < IN; k++) acc = fmaf(xs[k], w[k*OUT + o], acc);
        if (RELU) acc = fmaxf(acc, 0.f);
        y[row*OUT + o] = acc;
    }
}

extern "C" void kernel_launch(void* const* d_in, const int* in_sizes, int n_in,
                              void* d_out, int out_size) {
    const float* X       = (const float*)d_in[0];
    const float* conv1_w = (const float*)d_in[1];
    const float* bn1     = (const float*)d_in[2];
    const float* conv2_w = (const float*)d_in[3];
    const float* bn2     = (const float*)d_in[4];
    const float* conv3_w = (const float*)d_in[5];
    const float* bn3     = (const float*)d_in[6];
    const float* map2_w  = (const float*)d_in[7];
    const float* map2_b  = (const float*)d_in[8];
    const float* bn_map2 = (const float*)d_in[9];
    const float* g1_w = (const float*)d_in[10], *g1_b = (const float*)d_in[11], *bnA1 = (const float*)d_in[12];
    const float* th1_w = (const float*)d_in[13], *th1_b = (const float*)d_in[14], *bnM1 = (const float*)d_in[15];
    const float* g2_w = (const float*)d_in[16], *g2_b = (const float*)d_in[17], *bnA2 = (const float*)d_in[18];
    const float* th2_w = (const float*)d_in[19], *th2_b = (const float*)d_in[20], *bnM2 = (const float*)d_in[21];
    const float* fc1_w = (const float*)d_in[22], *fc1_b = (const float*)d_in[23];
    const float* fc2_w = (const float*)d_in[24], *fc2_b = (const float*)d_in[25];
    const float* fc3_w = (const float*)d_in[26], *fc3_b = (const float*)d_in[27];
    const float* fc4_w = (const float*)d_in[28], *fc4_b = (const float*)d_in[29];

    void* p;
    cudaGetSymbolAddress(&p, g_s1);   float* s1 = (float*)p;
    cudaGetSymbolAddress(&p, g_s2);   float* s2 = (float*)p;
    cudaGetSymbolAddress(&p, g_s3);   float* s3 = (float*)p;
    cudaGetSymbolAddress(&p, g_wt2);  float* wt2 = (float*)p;
    cudaGetSymbolAddress(&p, g_wt3);  float* wt3 = (float*)p;
    cudaGetSymbolAddress(&p, g_mp);   float* mp = (float*)p;
    cudaGetSymbolAddress(&p, g_a);    float* a  = (float*)p;
    cudaGetSymbolAddress(&p, g_f1);   float* f1 = (float*)p;
    cudaGetSymbolAddress(&p, g_f2);   float* f2 = (float*)p;
    cudaGetSymbolAddress(&p, g_adj1); float* adj1 = (float*)p;
    cudaGetSymbolAddress(&p, g_adj2); float* adj2 = (float*)p;
    cudaGetSymbolAddress(&p, g_feats);float* feats = (float*)p;
    cudaGetSymbolAddress(&p, g_t1);   float* t1 = (float*)p;
    cudaGetSymbolAddress(&p, g_t2);   float* t2 = (float*)p;
    cudaGetSymbolAddress(&p, g_t3);   float* t3 = (float*)p;

    k_wt<<<(128*64*3+255)/256, 256>>>(conv2_w, wt2, 64);
    k_wt<<<(128*128*3+255)/256, 256>>>(conv3_w, wt3, 128);
    k_conv1<<<dim3(768,3), 128>>>(X, conv1_w, bn1, s1);
    k_conv_mma<64,2,751,377><<<dim3(768,6), 512>>>(s1, wt2, bn2, s2);
    k_conv_mma<128,3,377,191><<<dim3(768,3), 512>>>(s2, wt3, bn3, s3);
    k_map2_mma<<<dim3(12,4,16), 256>>>(s3, map2_w, mp);
    k_combine<<<768, 256>>>(mp, map2_b, bn_map2, a);
    k_graphf<<<160, 256>>>(a, g1_w, g1_b, f1, 5, 1);
    k_graphf<<<96, 256>>>(a, g2_w, g2_b, f2, 3, 2);
    k_adj<<<160, 64>>>(f1, adj1);
    k_adj<<<96, 64>>>(f2, adj2);
    k_mpnn<<<160, 128>>>(a, adj1, bnA1, th1_w, th1_b, bnM1, feats, 5, 1, 0);
    k_mpnn<<<96, 128>>>(a, adj2, bnA2, th2_w, th2_b, bnM2, feats, 3, 2, 2560);
    k_fc<4096,256,true><<<32, 128>>>(feats, fc1_w, fc1_b, t1);
    k_fc<256,256,true><<<32, 128>>>(t1, fc2_w, fc2_b, t2);
    k_fc<256,128,true><<<32, 128>>>(t2, fc3_w, fc3_b, t3);
    k_fc<128,5,false><<<32, 128>>>(t3, fc4_w, fc4_b, (float*)d_out);
}